// round 2
// baseline (speedup 1.0000x reference)
#include <cuda_runtime.h>
#include <math.h>

// Problem constants
#define BB   4
#define NN   4096
#define CC   1024
#define HH   16
#define DDIM 64
#define BSZ  64
#define NBLK 64
#define MTOT (BB*NN)   // 16384

// Scratch (device globals: allocation-free per harness rules)
__device__ float g_q[(size_t)BB*HH*NN*DDIM];   // [b][h][n][d]
__device__ float g_k[(size_t)BB*HH*NN*DDIM];
__device__ float g_v[(size_t)BB*HH*NN*DDIM];
__device__ float g_o[(size_t)BB*NN*CC];        // [b][n][c]

// ---------------- packed f32x2 helpers (Blackwell FFMA2 path) ----------------
__device__ __forceinline__ unsigned long long pk2(float x, float y) {
    unsigned long long r;
    asm("mov.b64 %0, {%1, %2};" : "=l"(r) : "f"(x), "f"(y));
    return r;
}
__device__ __forceinline__ void upk2(unsigned long long v, float& x, float& y) {
    asm("mov.b64 {%0, %1}, %2;" : "=f"(x), "=f"(y) : "l"(v));
}
__device__ __forceinline__ unsigned long long ffma2(unsigned long long a,
                                                    unsigned long long b,
                                                    unsigned long long c) {
    unsigned long long d;
    asm("fma.rn.f32x2 %0, %1, %2, %3;" : "=l"(d) : "l"(a), "l"(b), "l"(c));
    return d;
}

// ---------------- GEMM: OUT[m][c] = sum_k X[m][k] * W[c][k] + bias[c] --------
// BM=BN=128, BK=16, 256 threads, 8x8 per thread, FFMA2 inner loop.
#define SM_STRIDE 132

// MODE 0: QKV (blockIdx.z = which), input X (harness ptr), scatter to g_q/g_k/g_v
// MODE 1: O-proj, input g_o (device symbol resolved IN DEVICE CODE), out to d_out
template<int MODE>
__global__ __launch_bounds__(256, 2)
void gemm_kernel(const float* __restrict__ Xin,
                 const float* __restrict__ W0,
                 const float* __restrict__ W1,
                 const float* __restrict__ W2,
                 const float* __restrict__ b0,
                 const float* __restrict__ b1,
                 const float* __restrict__ b2,
                 float* __restrict__ out)
{
    __shared__ float As[16 * SM_STRIDE];
    __shared__ float Bs[16 * SM_STRIDE];

    const int t  = threadIdx.x;
    const int m0 = blockIdx.x * 128;
    const int n0 = blockIdx.y * 128;

    // CRITICAL: device-symbol input resolved in device code, not host.
    const float* X = (MODE == 1) ? (const float*)g_o : Xin;

    const float* W    = W0;
    const float* bias = b0;
    if (MODE == 0) {
        if (blockIdx.z == 1) { W = W1; bias = b1; }
        else if (blockIdx.z == 2) { W = W2; bias = b2; }
    }

    const int tx = t & 15, ty = t >> 4;
    const int msub = ty * 8, nsub = tx * 8;

    unsigned long long acc[8][4];
#pragma unroll
    for (int i = 0; i < 8; i++)
#pragma unroll
        for (int j = 0; j < 4; j++) acc[i][j] = 0ull;

    for (int k0 = 0; k0 < CC; k0 += 16) {
        // load A tile (X rows) and B tile (W rows), both transposed to [k][row]
#pragma unroll
        for (int s = t; s < 512; s += 256) {
            int row = s >> 2;
            int k4  = (s & 3) << 2;
            float4 va = *(const float4*)&X[(size_t)(m0 + row) * CC + k0 + k4];
            As[(k4 + 0) * SM_STRIDE + row] = va.x;
            As[(k4 + 1) * SM_STRIDE + row] = va.y;
            As[(k4 + 2) * SM_STRIDE + row] = va.z;
            As[(k4 + 3) * SM_STRIDE + row] = va.w;
            float4 vb = *(const float4*)&W[(size_t)(n0 + row) * CC + k0 + k4];
            Bs[(k4 + 0) * SM_STRIDE + row] = vb.x;
            Bs[(k4 + 1) * SM_STRIDE + row] = vb.y;
            Bs[(k4 + 2) * SM_STRIDE + row] = vb.z;
            Bs[(k4 + 3) * SM_STRIDE + row] = vb.w;
        }
        __syncthreads();

#pragma unroll
        for (int kk = 0; kk < 16; kk++) {
            float a[8];
#pragma unroll
            for (int i = 0; i < 8; i++) a[i] = As[kk * SM_STRIDE + msub + i];
            unsigned long long bv[4];
#pragma unroll
            for (int j = 0; j < 4; j++) {
                float2 f = *(const float2*)&Bs[kk * SM_STRIDE + nsub + 2 * j];
                bv[j] = pk2(f.x, f.y);
            }
#pragma unroll
            for (int i = 0; i < 8; i++) {
                unsigned long long ap = pk2(a[i], a[i]);
#pragma unroll
                for (int j = 0; j < 4; j++)
                    acc[i][j] = ffma2(ap, bv[j], acc[i][j]);
            }
        }
        __syncthreads();
    }

    // epilogue
    const int which = (MODE == 0) ? blockIdx.z : 0;
    float* dst = g_q;
    if (MODE == 0) { if (which == 1) dst = g_k; else if (which == 2) dst = g_v; }

#pragma unroll
    for (int i = 0; i < 8; i++) {
        const int m   = m0 + msub + i;
        const int bb  = m >> 12;       // / NN
        const int tok = m & (NN - 1);
#pragma unroll
        for (int j = 0; j < 4; j++) {
            float x0, x1;
            upk2(acc[i][j], x0, x1);
            const int c = n0 + nsub + 2 * j;
            x0 += bias[c];
            x1 += bias[c + 1];
            if (MODE == 0) {
                const int h  = c >> 6;
                const int dd = c & 63;
                size_t o = (((size_t)bb * HH + h) * NN + tok) * DDIM + dd;
                dst[o]     = x0;
                dst[o + 1] = x1;
            } else {
                size_t o = (size_t)m * CC + c;
                out[o]     = x0;
                out[o + 1] = x1;
            }
        }
    }
}

// ---------------- Attention: one CTA per (b, h, blk) -------------------------
// Effective window is blocks [blk-1, blk] (right block fully causal-masked:
// abs_k = (blk+1)*64 + j' needs abs_q = blk*64 + i >= abs_k, impossible).
// smem: sQ[kk][i] (64x65), sKV union (K^T 64x136 / V 128x68), sS[i][j] (64x136)
#define SQ_OFF  0
#define SKV_OFF 4160
#define SS_OFF  (4160 + 8704)
#define ATT_SMEM_FLOATS (4160 + 8704 + 8704)
#define ATT_SMEM_BYTES  (ATT_SMEM_FLOATS * 4)

__global__ __launch_bounds__(256)
void attn_kernel()
{
    extern __shared__ float sm[];
    float* sQ  = sm + SQ_OFF;
    float* sKV = sm + SKV_OFF;
    float* sS  = sm + SS_OFF;

    const int blk = blockIdx.x;
    const int h   = blockIdx.y;
    const int b   = blockIdx.z;
    const int t   = threadIdx.x;

    const size_t base = ((size_t)(b * HH + h)) * NN * DDIM;

    // load Q transposed: sQ[kk][i]
#pragma unroll
    for (int s = t; s < 1024; s += 256) {
        int i  = s >> 4;
        int k4 = (s & 15) << 2;
        float4 v = *(const float4*)&g_q[base + (size_t)(blk * BSZ + i) * DDIM + k4];
        sQ[(k4 + 0) * 65 + i] = v.x;
        sQ[(k4 + 1) * 65 + i] = v.y;
        sQ[(k4 + 2) * 65 + i] = v.z;
        sQ[(k4 + 3) * 65 + i] = v.w;
    }
    // load K window transposed: sKV[kk][j], tokens (blk-1)*64 + j, j in [0,128)
#pragma unroll
    for (int s = t; s < 2048; s += 256) {
        int j  = s >> 4;
        int k4 = (s & 15) << 2;
        int tokrel = (blk - 1) * BSZ + j;
        if (tokrel >= 0) {
            float4 v = *(const float4*)&g_k[base + (size_t)tokrel * DDIM + k4];
            sKV[(k4 + 0) * 136 + j] = v.x;
            sKV[(k4 + 1) * 136 + j] = v.y;
            sKV[(k4 + 2) * 136 + j] = v.z;
            sKV[(k4 + 3) * 136 + j] = v.w;
        }
    }
    __syncthreads();

    // scores: thread (tx,ty) owns i in [ty*4, +4), j in [tx*8, +8)
    const int tx = t & 15, ty = t >> 4;
    const int i0 = ty * 4, j0 = tx * 8;

    unsigned long long sacc[4][4];
#pragma unroll
    for (int ii = 0; ii < 4; ii++)
#pragma unroll
        for (int jj = 0; jj < 4; jj++) sacc[ii][jj] = 0ull;

#pragma unroll 8
    for (int kk = 0; kk < 64; kk++) {
        unsigned long long bv[4];
#pragma unroll
        for (int jj = 0; jj < 4; jj++) {
            float2 f = *(const float2*)&sKV[kk * 136 + j0 + 2 * jj];
            bv[jj] = pk2(f.x, f.y);
        }
#pragma unroll
        for (int ii = 0; ii < 4; ii++) {
            float a = sQ[kk * 65 + i0 + ii];
            unsigned long long ap = pk2(a, a);
#pragma unroll
            for (int jj = 0; jj < 4; jj++)
                sacc[ii][jj] = ffma2(ap, bv[jj], sacc[ii][jj]);
        }
    }

    // unpack + mask + scale
    float sc[4][8];
#pragma unroll
    for (int ii = 0; ii < 4; ii++) {
        const int i = i0 + ii;
#pragma unroll
        for (int jj = 0; jj < 4; jj++) {
            float x0, x1;
            upk2(sacc[ii][jj], x0, x1);
            int j = j0 + 2 * jj;
            bool v0 = (j     <= 64 + i) && (j     >= 64 || blk > 0);
            bool v1 = (j + 1 <= 64 + i) && (j + 1 >= 64 || blk > 0);
            sc[ii][2 * jj]     = v0 ? x0 * 0.125f : -1e30f;
            sc[ii][2 * jj + 1] = v1 ? x1 * 0.125f : -1e30f;
        }
    }

    // softmax across the 16-lane tx-group (half-warp): max, exp, sum, norm
    float mx[4];
#pragma unroll
    for (int ii = 0; ii < 4; ii++) {
        float m = sc[ii][0];
#pragma unroll
        for (int jj = 1; jj < 8; jj++) m = fmaxf(m, sc[ii][jj]);
        mx[ii] = m;
    }
#pragma unroll
    for (int off = 8; off >= 1; off >>= 1)
#pragma unroll
        for (int ii = 0; ii < 4; ii++)
            mx[ii] = fmaxf(mx[ii], __shfl_xor_sync(0xffffffffu, mx[ii], off));

    float sum[4];
#pragma unroll
    for (int ii = 0; ii < 4; ii++) {
        float s = 0.f;
#pragma unroll
        for (int jj = 0; jj < 8; jj++) {
            float e = __expf(sc[ii][jj] - mx[ii]);
            sc[ii][jj] = e;
            s += e;
        }
        sum[ii] = s;
    }
#pragma unroll
    for (int off = 8; off >= 1; off >>= 1)
#pragma unroll
        for (int ii = 0; ii < 4; ii++)
            sum[ii] += __shfl_xor_sync(0xffffffffu, sum[ii], off);

#pragma unroll
    for (int ii = 0; ii < 4; ii++) {
        float inv = 1.f / sum[ii];
#pragma unroll
        for (int jj = 0; jj < 8; jj++)
            sS[(i0 + ii) * 136 + j0 + jj] = sc[ii][jj] * inv;
    }
    __syncthreads();   // all K reads & p writes done

    // load V into sKV (natural layout [j][dd], stride 68). Zero masked rows.
#pragma unroll
    for (int s = t; s < 2048; s += 256) {
        int j   = s >> 4;
        int dd0 = (s & 15) << 2;
        int tokrel = (blk - 1) * BSZ + j;
        float4 v = make_float4(0.f, 0.f, 0.f, 0.f);
        if (tokrel >= 0)
            v = *(const float4*)&g_v[base + (size_t)tokrel * DDIM + dd0];
        *(float4*)&sKV[j * 68 + dd0] = v;
    }
    __syncthreads();

    // PV: thread (tx,ty) owns i in [ty*4,+4), dd in [tx*4,+4)
    const int dd0 = tx * 4;
    unsigned long long oa[4][2];
#pragma unroll
    for (int ii = 0; ii < 4; ii++) { oa[ii][0] = 0ull; oa[ii][1] = 0ull; }

#pragma unroll 8
    for (int j = 0; j < 128; j++) {
        float2 v0 = *(const float2*)&sKV[j * 68 + dd0];
        float2 v1 = *(const float2*)&sKV[j * 68 + dd0 + 2];
        unsigned long long bv0 = pk2(v0.x, v0.y);
        unsigned long long bv1 = pk2(v1.x, v1.y);
#pragma unroll
        for (int ii = 0; ii < 4; ii++) {
            float p = sS[(i0 + ii) * 136 + j];
            unsigned long long pp = pk2(p, p);
            oa[ii][0] = ffma2(pp, bv0, oa[ii][0]);
            oa[ii][1] = ffma2(pp, bv1, oa[ii][1]);
        }
    }

#pragma unroll
    for (int ii = 0; ii < 4; ii++) {
        const int tok = blk * BSZ + i0 + ii;
        float o0, o1, o2, o3;
        upk2(oa[ii][0], o0, o1);
        upk2(oa[ii][1], o2, o3);
        float4 w = make_float4(o0, o1, o2, o3);
        *(float4*)&g_o[((size_t)(b * NN) + tok) * CC + h * DDIM + dd0] = w;
    }
}

// ---------------- launch ------------------------------------------------------
extern "C" void kernel_launch(void* const* d_in, const int* in_sizes, int n_in,
                              void* d_out, int out_size)
{
    const float* x  = (const float*)d_in[0];
    const float* Wq = (const float*)d_in[1];
    const float* bq = (const float*)d_in[2];
    const float* Wk = (const float*)d_in[3];
    const float* bk = (const float*)d_in[4];
    const float* Wv = (const float*)d_in[5];
    const float* bv = (const float*)d_in[6];
    const float* Wo = (const float*)d_in[7];
    const float* bo = (const float*)d_in[8];
    float* out = (float*)d_out;

    cudaFuncSetAttribute(attn_kernel,
                         cudaFuncAttributeMaxDynamicSharedMemorySize,
                         ATT_SMEM_BYTES);

    // QKV projections (z selects q/k/v)
    dim3 g1(MTOT / 128, CC / 128, 3);
    gemm_kernel<0><<<g1, 256>>>(x, Wq, Wk, Wv, bq, bk, bv, nullptr);

    // block-sparse attention
    attn_kernel<<<dim3(NBLK, HH, BB), 256, ATT_SMEM_BYTES>>>();

    // output projection (input = g_o, resolved in device code)
    dim3 g2(MTOT / 128, CC / 128, 1);
    gemm_kernel<1><<<g2, 256>>>(nullptr, Wo, nullptr, nullptr, bo, nullptr, nullptr, out);
}

// round 4
// speedup vs baseline: 1.7286x; 1.7286x over previous
#include <cuda_runtime.h>
#include <cuda_bf16.h>
#include <math.h>
#include <stdint.h>

// Problem constants
#define BB   4
#define NN   4096
#define CC   1024
#define HH   16
#define DDIM 64
#define BSZ  64
#define NBLK 64
#define MTOT (BB*NN)   // 16384

// ---------------- scratch (device globals, allocation-free) ------------------
__device__ float g_q[(size_t)BB*HH*NN*DDIM];   // [b][h][n][d] fp32
__device__ float g_k[(size_t)BB*HH*NN*DDIM];
__device__ float g_v[(size_t)BB*HH*NN*DDIM];

__device__ __nv_bfloat16 g_xhi[(size_t)MTOT*CC];   // split-bf16 activations
__device__ __nv_bfloat16 g_xlo[(size_t)MTOT*CC];
__device__ __nv_bfloat16 g_whi[(size_t)4*CC*CC];   // Wq,Wk,Wv,Wo concat
__device__ __nv_bfloat16 g_wlo[(size_t)4*CC*CC];
__device__ __nv_bfloat16 g_ohi[(size_t)MTOT*CC];   // attention out split
__device__ __nv_bfloat16 g_olo[(size_t)MTOT*CC];

// ---------------- PTX helpers (all base sm_103 target, no 'a' features) ------
__device__ __forceinline__ uint32_t smem_u32(const void* p) {
    uint32_t a;
    asm("{ .reg .u64 t; cvta.to.shared.u64 t, %1; cvt.u32.u64 %0, t; }"
        : "=r"(a) : "l"(p));
    return a;
}
__device__ __forceinline__ void ldsm4(unsigned* r, uint32_t addr) {
    asm volatile("ldmatrix.sync.aligned.m8n8.x4.shared.b16 {%0,%1,%2,%3}, [%4];"
                 : "=r"(r[0]), "=r"(r[1]), "=r"(r[2]), "=r"(r[3]) : "r"(addr));
}
__device__ __forceinline__ void mma16816(float* d, const unsigned* a, const unsigned* b) {
    asm volatile(
        "mma.sync.aligned.m16n8k16.row.col.f32.bf16.bf16.f32 "
        "{%0,%1,%2,%3}, {%4,%5,%6,%7}, {%8,%9}, {%0,%1,%2,%3};"
        : "+f"(d[0]), "+f"(d[1]), "+f"(d[2]), "+f"(d[3])
        : "r"(a[0]), "r"(a[1]), "r"(a[2]), "r"(a[3]), "r"(b[0]), "r"(b[1]));
}
__device__ __forceinline__ void cpasync16(uint32_t saddr, const void* g) {
    asm volatile("cp.async.cg.shared.global [%0], [%1], 16;" :: "r"(saddr), "l"(g));
}
#define CP_COMMIT()  asm volatile("cp.async.commit_group;" ::: "memory")
#define CP_WAIT1()   asm volatile("cp.async.wait_group 1;" ::: "memory")
#define CP_WAIT0()   asm volatile("cp.async.wait_group 0;" ::: "memory")

// ---------------- split-fp32 -> (hi, lo) bf16 conversion ---------------------
__global__ void convert_kernel(const float* __restrict__ src, int sel, int n4)
{
    __nv_bfloat16* hi;
    __nv_bfloat16* lo;
    if (sel == 0) { hi = g_xhi; lo = g_xlo; }
    else          { hi = g_whi + (size_t)(sel - 1) * CC * CC;
                    lo = g_wlo + (size_t)(sel - 1) * CC * CC; }
    int i = blockIdx.x * blockDim.x + threadIdx.x;
    if (i >= n4) return;
    float4 v = ((const float4*)src)[i];
    __nv_bfloat16 h0 = __float2bfloat16_rn(v.x);
    __nv_bfloat16 h1 = __float2bfloat16_rn(v.y);
    __nv_bfloat16 h2 = __float2bfloat16_rn(v.z);
    __nv_bfloat16 h3 = __float2bfloat16_rn(v.w);
    __nv_bfloat162 ph0; ph0.x = h0; ph0.y = h1;
    __nv_bfloat162 ph1; ph1.x = h2; ph1.y = h3;
    ((__nv_bfloat162*)hi)[i * 2]     = ph0;
    ((__nv_bfloat162*)hi)[i * 2 + 1] = ph1;
    __nv_bfloat162 pl0 = __floats2bfloat162_rn(v.x - __bfloat162float(h0),
                                               v.y - __bfloat162float(h1));
    __nv_bfloat162 pl1 = __floats2bfloat162_rn(v.z - __bfloat162float(h2),
                                               v.w - __bfloat162float(h3));
    ((__nv_bfloat162*)lo)[i * 2]     = pl0;
    ((__nv_bfloat162*)lo)[i * 2 + 1] = pl1;
}

// ---------------- HMMA split-bf16 GEMM ---------------------------------------
// OUT[m][c] = sum_k X[m][k]*W[c][k] + bias[c]; CTA tile 128x128, BK=32.
// smem tile rows padded to 80B (5 x 16B chunks; gcd(5,8)=1 -> conflict-free
// ldmatrix). Per stage: Ahi, Alo, Bhi, Blo tiles of 128 rows x 64B data.
#define TILE_B 10240            // 128 * 80
#define STAGE_B (4 * TILE_B)    // 40960
#define GEMM_SMEM (2 * STAGE_B) // 81920

template<int MODE>
__global__ __launch_bounds__(256, 2)
void gemm_mma(const float* __restrict__ b0,
              const float* __restrict__ b1,
              const float* __restrict__ b2,
              float* __restrict__ out)
{
    extern __shared__ char smc[];
    const uint32_t sb = smem_u32(smc);
    const int t    = threadIdx.x;
    const int w    = t >> 5;
    const int lane = t & 31;
    const int wm   = w & 3;          // m-warp: rows wm*32 .. +32
    const int wn   = w >> 2;         // n-warp: cols wn*64 .. +64
    const int m0   = blockIdx.x * 128;
    const int n0   = blockIdx.y * 128;
    const int widx = (MODE == 0) ? (int)blockIdx.z : 3;

    const __nv_bfloat16* Ahi = (MODE == 0) ? g_xhi : g_ohi;
    const __nv_bfloat16* Alo = (MODE == 0) ? g_xlo : g_olo;
    const __nv_bfloat16* Bhi = g_whi + (size_t)widx * CC * CC;
    const __nv_bfloat16* Blo = g_wlo + (size_t)widx * CC * CC;
    const float* bias = b0;
    if (MODE == 0) { if (blockIdx.z == 1) bias = b1; else if (blockIdx.z == 2) bias = b2; }

    // per-thread copy roles: 4 tiles * 128 rows * 4 chunks = 2048 chunks / 256 thr
    // role i: id = i*256 + t -> tile(id>>9), r(id&127), c((id>>7)&3)
    float acc[2][8][4];
#pragma unroll
    for (int a = 0; a < 2; a++)
#pragma unroll
        for (int n = 0; n < 8; n++)
#pragma unroll
            for (int k = 0; k < 4; k++) acc[a][n][k] = 0.f;

    // ldmatrix per-lane offsets
    const uint32_t aoff = (uint32_t)((lane & 15) * 80 + (lane >> 4) * 16);
    const uint32_t boff = (uint32_t)(((lane & 7) + (lane >> 4) * 8) * 80 + ((lane >> 3) & 1) * 16);

    auto issue = [&](int ch) {
        const int buf = ch & 1;
        const int k0  = ch * 32;
        const uint32_t stage = sb + buf * STAGE_B;
#pragma unroll
        for (int i = 0; i < 8; i++) {
            int id   = i * 256 + t;
            int tile = id >> 9;
            int idx  = id & 511;
            int r    = idx & 127;
            int c    = (idx >> 7) & 3;
            const __nv_bfloat16* gp;
            int row;
            if (tile < 2) { row = m0 + r; gp = (tile == 0) ? Ahi : Alo; }
            else          { row = n0 + r; gp = (tile == 2) ? Bhi : Blo; }
            cpasync16(stage + tile * TILE_B + (uint32_t)(r * 80 + c * 16),
                      gp + (size_t)row * CC + k0 + c * 8);
        }
        CP_COMMIT();
    };

    issue(0);
    for (int ch = 0; ch < 32; ch++) {
        if (ch + 1 < 32) { issue(ch + 1); CP_WAIT1(); }
        else             { CP_WAIT0(); }
        __syncthreads();

        const uint32_t stage = sb + (ch & 1) * STAGE_B;
#pragma unroll
        for (int s = 0; s < 2; s++) {      // two k16 steps within BK=32
            unsigned ahi[2][4], alo[2][4];
#pragma unroll
            for (int mt = 0; mt < 2; mt++) {
                uint32_t ra = stage + (uint32_t)((wm * 32 + mt * 16) * 80) + aoff + s * 32;
                ldsm4(ahi[mt], ra);
                ldsm4(alo[mt], ra + TILE_B);
            }
#pragma unroll
            for (int np = 0; np < 4; np++) {   // n8-pairs: covers n = np*16 .. +16
                unsigned bhi[4], blo[4];
                uint32_t rb = stage + 2 * TILE_B
                            + (uint32_t)((wn * 64 + np * 16) * 80) + boff + s * 32;
                ldsm4(bhi, rb);
                ldsm4(blo, rb + TILE_B);
#pragma unroll
                for (int mt = 0; mt < 2; mt++) {
#pragma unroll
                    for (int nh = 0; nh < 2; nh++) {
                        float* d = acc[mt][np * 2 + nh];
                        mma16816(d, ahi[mt], &bhi[2 * nh]);
                        mma16816(d, ahi[mt], &blo[2 * nh]);
                        mma16816(d, alo[mt], &bhi[2 * nh]);
                    }
                }
            }
        }
        __syncthreads();
    }

    // epilogue: D frag mapping: d0,d1 -> row l/4, cols 2(l%4),+1 ; d2,d3 -> row+8
    float* dst = g_q;
    if (MODE == 0) { if (blockIdx.z == 1) dst = g_k; else if (blockIdx.z == 2) dst = g_v; }

#pragma unroll
    for (int mt = 0; mt < 2; mt++) {
#pragma unroll
        for (int nt = 0; nt < 8; nt++) {
            float* d = acc[mt][nt];
            const int col = n0 + wn * 64 + nt * 8 + 2 * (lane & 3);
            const float bv0 = bias[col], bv1 = bias[col + 1];
            const int r0 = m0 + wm * 32 + mt * 16 + (lane >> 2);
#pragma unroll
            for (int half = 0; half < 2; half++) {
                const int r = r0 + half * 8;
                float2 v = make_float2(d[2 * half] + bv0, d[2 * half + 1] + bv1);
                if (MODE == 0) {
                    const int bb  = r >> 12;
                    const int tok = r & (NN - 1);
                    const int h   = col >> 6;
                    const int dd  = col & 63;
                    *(float2*)&dst[(((size_t)bb * HH + h) * NN + tok) * DDIM + dd] = v;
                } else {
                    *(float2*)&out[(size_t)r * CC + col] = v;
                }
            }
        }
    }
}

// ---------------- Attention: one CTA per (b, h, blk) -------------------------
// Window blocks [blk-1, blk]; right block fully causal-masked. fp32 math.
// Epilogue writes split-bf16 directly to g_ohi/g_olo.
#define SQ_OFF  0
#define SKV_OFF 4160
#define SS_OFF  (4160 + 8704)
#define ATT_SMEM_FLOATS (4160 + 8704 + 8704)
#define ATT_SMEM_BYTES  (ATT_SMEM_FLOATS * 4)

__device__ __forceinline__ unsigned long long pk2(float x, float y) {
    unsigned long long r;
    asm("mov.b64 %0, {%1, %2};" : "=l"(r) : "f"(x), "f"(y));
    return r;
}
__device__ __forceinline__ void upk2(unsigned long long v, float& x, float& y) {
    asm("mov.b64 {%0, %1}, %2;" : "=f"(x), "=f"(y) : "l"(v));
}
__device__ __forceinline__ unsigned long long ffma2(unsigned long long a,
                                                    unsigned long long b,
                                                    unsigned long long c) {
    unsigned long long d;
    asm("fma.rn.f32x2 %0, %1, %2, %3;" : "=l"(d) : "l"(a), "l"(b), "l"(c));
    return d;
}

__global__ __launch_bounds__(256)
void attn_kernel()
{
    extern __shared__ float sm[];
    float* sQ  = sm + SQ_OFF;
    float* sKV = sm + SKV_OFF;
    float* sS  = sm + SS_OFF;

    const int blk = blockIdx.x;
    const int h   = blockIdx.y;
    const int b   = blockIdx.z;
    const int t   = threadIdx.x;

    const size_t base = ((size_t)(b * HH + h)) * NN * DDIM;

#pragma unroll
    for (int s = t; s < 1024; s += 256) {
        int i  = s >> 4;
        int k4 = (s & 15) << 2;
        float4 v = *(const float4*)&g_q[base + (size_t)(blk * BSZ + i) * DDIM + k4];
        sQ[(k4 + 0) * 65 + i] = v.x;
        sQ[(k4 + 1) * 65 + i] = v.y;
        sQ[(k4 + 2) * 65 + i] = v.z;
        sQ[(k4 + 3) * 65 + i] = v.w;
    }
#pragma unroll
    for (int s = t; s < 2048; s += 256) {
        int j  = s >> 4;
        int k4 = (s & 15) << 2;
        int tokrel = (blk - 1) * BSZ + j;
        if (tokrel >= 0) {
            float4 v = *(const float4*)&g_k[base + (size_t)tokrel * DDIM + k4];
            sKV[(k4 + 0) * 136 + j] = v.x;
            sKV[(k4 + 1) * 136 + j] = v.y;
            sKV[(k4 + 2) * 136 + j] = v.z;
            sKV[(k4 + 3) * 136 + j] = v.w;
        }
    }
    __syncthreads();

    const int tx = t & 15, ty = t >> 4;
    const int i0 = ty * 4, j0 = tx * 8;

    unsigned long long sacc[4][4];
#pragma unroll
    for (int ii = 0; ii < 4; ii++)
#pragma unroll
        for (int jj = 0; jj < 4; jj++) sacc[ii][jj] = 0ull;

#pragma unroll 8
    for (int kk = 0; kk < 64; kk++) {
        unsigned long long bv[4];
#pragma unroll
        for (int jj = 0; jj < 4; jj++) {
            float2 f = *(const float2*)&sKV[kk * 136 + j0 + 2 * jj];
            bv[jj] = pk2(f.x, f.y);
        }
#pragma unroll
        for (int ii = 0; ii < 4; ii++) {
            float a = sQ[kk * 65 + i0 + ii];
            unsigned long long ap = pk2(a, a);
#pragma unroll
            for (int jj = 0; jj < 4; jj++)
                sacc[ii][jj] = ffma2(ap, bv[jj], sacc[ii][jj]);
        }
    }

    float sc[4][8];
#pragma unroll
    for (int ii = 0; ii < 4; ii++) {
        const int i = i0 + ii;
#pragma unroll
        for (int jj = 0; jj < 4; jj++) {
            float x0, x1;
            upk2(sacc[ii][jj], x0, x1);
            int j = j0 + 2 * jj;
            bool v0 = (j     <= 64 + i) && (j     >= 64 || blk > 0);
            bool v1 = (j + 1 <= 64 + i) && (j + 1 >= 64 || blk > 0);
            sc[ii][2 * jj]     = v0 ? x0 * 0.125f : -1e30f;
            sc[ii][2 * jj + 1] = v1 ? x1 * 0.125f : -1e30f;
        }
    }

    float mx[4];
#pragma unroll
    for (int ii = 0; ii < 4; ii++) {
        float m = sc[ii][0];
#pragma unroll
        for (int jj = 1; jj < 8; jj++) m = fmaxf(m, sc[ii][jj]);
        mx[ii] = m;
    }
#pragma unroll
    for (int off = 8; off >= 1; off >>= 1)
#pragma unroll
        for (int ii = 0; ii < 4; ii++)
            mx[ii] = fmaxf(mx[ii], __shfl_xor_sync(0xffffffffu, mx[ii], off));

    float sum[4];
#pragma unroll
    for (int ii = 0; ii < 4; ii++) {
        float s = 0.f;
#pragma unroll
        for (int jj = 0; jj < 8; jj++) {
            float e = __expf(sc[ii][jj] - mx[ii]);
            sc[ii][jj] = e;
            s += e;
        }
        sum[ii] = s;
    }
#pragma unroll
    for (int off = 8; off >= 1; off >>= 1)
#pragma unroll
        for (int ii = 0; ii < 4; ii++)
            sum[ii] += __shfl_xor_sync(0xffffffffu, sum[ii], off);

#pragma unroll
    for (int ii = 0; ii < 4; ii++) {
        float inv = 1.f / sum[ii];
#pragma unroll
        for (int jj = 0; jj < 8; jj++)
            sS[(i0 + ii) * 136 + j0 + jj] = sc[ii][jj] * inv;
    }
    __syncthreads();

#pragma unroll
    for (int s = t; s < 2048; s += 256) {
        int j   = s >> 4;
        int dd0 = (s & 15) << 2;
        int tokrel = (blk - 1) * BSZ + j;
        float4 v = make_float4(0.f, 0.f, 0.f, 0.f);
        if (tokrel >= 0)
            v = *(const float4*)&g_v[base + (size_t)tokrel * DDIM + dd0];
        *(float4*)&sKV[j * 68 + dd0] = v;
    }
    __syncthreads();

    const int dd0 = tx * 4;
    unsigned long long oa[4][2];
#pragma unroll
    for (int ii = 0; ii < 4; ii++) { oa[ii][0] = 0ull; oa[ii][1] = 0ull; }

#pragma unroll 8
    for (int j = 0; j < 128; j++) {
        float2 v0 = *(const float2*)&sKV[j * 68 + dd0];
        float2 v1 = *(const float2*)&sKV[j * 68 + dd0 + 2];
        unsigned long long bv0 = pk2(v0.x, v0.y);
        unsigned long long bv1 = pk2(v1.x, v1.y);
#pragma unroll
        for (int ii = 0; ii < 4; ii++) {
            float p = sS[(i0 + ii) * 136 + j];
            unsigned long long pp = pk2(p, p);
            oa[ii][0] = ffma2(pp, bv0, oa[ii][0]);
            oa[ii][1] = ffma2(pp, bv1, oa[ii][1]);
        }
    }

    // epilogue: write split-bf16 directly (input for O-projection GEMM)
#pragma unroll
    for (int ii = 0; ii < 4; ii++) {
        const int tok = blk * BSZ + i0 + ii;
        float o0, o1, o2, o3;
        upk2(oa[ii][0], o0, o1);
        upk2(oa[ii][1], o2, o3);
        __nv_bfloat16 h0 = __float2bfloat16_rn(o0);
        __nv_bfloat16 h1 = __float2bfloat16_rn(o1);
        __nv_bfloat16 h2 = __float2bfloat16_rn(o2);
        __nv_bfloat16 h3 = __float2bfloat16_rn(o3);
        size_t off = ((size_t)(b * NN) + tok) * CC + h * DDIM + dd0;
        __nv_bfloat162 p0; p0.x = h0; p0.y = h1;
        __nv_bfloat162 p1; p1.x = h2; p1.y = h3;
        *(__nv_bfloat162*)&g_ohi[off]     = p0;
        *(__nv_bfloat162*)&g_ohi[off + 2] = p1;
        __nv_bfloat162 l0 = __floats2bfloat162_rn(o0 - __bfloat162float(h0),
                                                  o1 - __bfloat162float(h1));
        __nv_bfloat162 l1 = __floats2bfloat162_rn(o2 - __bfloat162float(h2),
                                                  o3 - __bfloat162float(h3));
        *(__nv_bfloat162*)&g_olo[off]     = l0;
        *(__nv_bfloat162*)&g_olo[off + 2] = l1;
    }
}

// ---------------- launch ------------------------------------------------------
extern "C" void kernel_launch(void* const* d_in, const int* in_sizes, int n_in,
                              void* d_out, int out_size)
{
    const float* x  = (const float*)d_in[0];
    const float* Wq = (const float*)d_in[1];
    const float* bq = (const float*)d_in[2];
    const float* Wk = (const float*)d_in[3];
    const float* bk = (const float*)d_in[4];
    const float* Wv = (const float*)d_in[5];
    const float* bv = (const float*)d_in[6];
    const float* Wo = (const float*)d_in[7];
    const float* bo = (const float*)d_in[8];
    float* out = (float*)d_out;

    cudaFuncSetAttribute(attn_kernel,
                         cudaFuncAttributeMaxDynamicSharedMemorySize, ATT_SMEM_BYTES);
    cudaFuncSetAttribute(gemm_mma<0>,
                         cudaFuncAttributeMaxDynamicSharedMemorySize, GEMM_SMEM);
    cudaFuncSetAttribute(gemm_mma<1>,
                         cudaFuncAttributeMaxDynamicSharedMemorySize, GEMM_SMEM);

    // split fp32 -> hi/lo bf16
    {
        int n4 = MTOT * CC / 4;
        convert_kernel<<<(n4 + 255) / 256, 256>>>(x, 0, n4);
        int w4 = CC * CC / 4;
        convert_kernel<<<(w4 + 255) / 256, 256>>>(Wq, 1, w4);
        convert_kernel<<<(w4 + 255) / 256, 256>>>(Wk, 2, w4);
        convert_kernel<<<(w4 + 255) / 256, 256>>>(Wv, 3, w4);
        convert_kernel<<<(w4 + 255) / 256, 256>>>(Wo, 4, w4);
    }

    // QKV projections on tensor cores (HMMA)
    dim3 g1(MTOT / 128, CC / 128, 3);
    gemm_mma<0><<<g1, 256, GEMM_SMEM>>>(bq, bk, bv, nullptr);

    // block-sparse attention (fp32), writes split-bf16 output
    attn_kernel<<<dim3(NBLK, HH, BB), 256, ATT_SMEM_BYTES>>>();

    // output projection on tensor cores
    dim3 g2(MTOT / 128, CC / 128, 1);
    gemm_mma<1><<<g2, 256, GEMM_SMEM>>>(bo, nullptr, nullptr, out);
}

// round 6
// speedup vs baseline: 2.1830x; 1.2629x over previous
#include <cuda_runtime.h>
#include <cuda_fp16.h>
#include <math.h>
#include <stdint.h>

// Problem constants
#define BB   4
#define NN   4096
#define CC   1024
#define HH   16
#define DDIM 64
#define BSZ  64
#define NBLK 64
#define MTOT (BB*NN)   // 16384

// ---------------- scratch (device globals, allocation-free) ------------------
__device__ float g_q[(size_t)BB*HH*NN*DDIM];   // [b][h][n][d] fp32
__device__ float g_k[(size_t)BB*HH*NN*DDIM];
__device__ float g_v[(size_t)BB*HH*NN*DDIM];

__device__ __half g_xhi[(size_t)MTOT*CC];   // split-fp16 activations
__device__ __half g_xlo[(size_t)MTOT*CC];
__device__ __half g_whi[(size_t)4*CC*CC];   // Wq,Wk,Wv,Wo hi only (fp16)
__device__ __half g_ohi[(size_t)MTOT*CC];   // attention out split
__device__ __half g_olo[(size_t)MTOT*CC];

// ---------------- PTX helpers (all base sm_103 target, no 'a' features) ------
__device__ __forceinline__ uint32_t smem_u32(const void* p) {
    uint32_t a;
    asm("{ .reg .u64 t; cvta.to.shared.u64 t, %1; cvt.u32.u64 %0, t; }"
        : "=r"(a) : "l"(p));
    return a;
}
__device__ __forceinline__ void ldsm4(unsigned* r, uint32_t addr) {
    asm volatile("ldmatrix.sync.aligned.m8n8.x4.shared.b16 {%0,%1,%2,%3}, [%4];"
                 : "=r"(r[0]), "=r"(r[1]), "=r"(r[2]), "=r"(r[3]) : "r"(addr));
}
// fp16 inputs, fp32 accumulate
__device__ __forceinline__ void mma16816_f32(float* d, const unsigned* a, const unsigned* b) {
    asm volatile(
        "mma.sync.aligned.m16n8k16.row.col.f32.f16.f16.f32 "
        "{%0,%1,%2,%3}, {%4,%5,%6,%7}, {%8,%9}, {%0,%1,%2,%3};"
        : "+f"(d[0]), "+f"(d[1]), "+f"(d[2]), "+f"(d[3])
        : "r"(a[0]), "r"(a[1]), "r"(a[2]), "r"(a[3]), "r"(b[0]), "r"(b[1]));
}
// fp16 inputs, fp16 accumulate (2x rate on most archs) — used for the lo product
__device__ __forceinline__ void mma16816_f16(unsigned* d, const unsigned* a, const unsigned* b) {
    asm volatile(
        "mma.sync.aligned.m16n8k16.row.col.f16.f16.f16.f16 "
        "{%0,%1}, {%2,%3,%4,%5}, {%6,%7}, {%0,%1};"
        : "+r"(d[0]), "+r"(d[1])
        : "r"(a[0]), "r"(a[1]), "r"(a[2]), "r"(a[3]), "r"(b[0]), "r"(b[1]));
}
__device__ __forceinline__ void cpasync16(uint32_t saddr, const void* g) {
    asm volatile("cp.async.cg.shared.global [%0], [%1], 16;" :: "r"(saddr), "l"(g));
}
#define CP_COMMIT()  asm volatile("cp.async.commit_group;" ::: "memory")
#define CP_WAIT1()   asm volatile("cp.async.wait_group 1;" ::: "memory")
#define CP_WAIT0()   asm volatile("cp.async.wait_group 0;" ::: "memory")

// ---------------- split-fp32 -> fp16 conversion ------------------------------
// sel 0: x -> g_xhi + g_xlo (hi/lo pair). sel 1..4: W -> g_whi[(sel-1)] hi only.
__global__ void convert_kernel(const float* __restrict__ src, int sel, int n4)
{
    int i = blockIdx.x * blockDim.x + threadIdx.x;
    if (i >= n4) return;
    float4 v = ((const float4*)src)[i];
    __half h0 = __float2half_rn(v.x);
    __half h1 = __float2half_rn(v.y);
    __half h2 = __float2half_rn(v.z);
    __half h3 = __float2half_rn(v.w);
    __half2 ph0; ph0.x = h0; ph0.y = h1;
    __half2 ph1; ph1.x = h2; ph1.y = h3;
    if (sel == 0) {
        ((__half2*)g_xhi)[i * 2]     = ph0;
        ((__half2*)g_xhi)[i * 2 + 1] = ph1;
        __half2 pl0 = __floats2half2_rn(v.x - __half2float(h0),
                                        v.y - __half2float(h1));
        __half2 pl1 = __floats2half2_rn(v.z - __half2float(h2),
                                        v.w - __half2float(h3));
        ((__half2*)g_xlo)[i * 2]     = pl0;
        ((__half2*)g_xlo)[i * 2 + 1] = pl1;
    } else {
        __half* hi = g_whi + (size_t)(sel - 1) * CC * CC;
        ((__half2*)hi)[i * 2]     = ph0;
        ((__half2*)hi)[i * 2 + 1] = ph1;
    }
}

// ---------------- HMMA split-fp16 GEMM ---------------------------------------
// OUT[m][c] = sum_k X[m][k]*W[c][k] + bias[c]; CTA tile 128x128, BK=32.
// Products: Ahi*Bhi (fp32 acc) + Alo*Bhi (fp16 acc).
// smem rows padded to 80B (gcd(5,8)=1 -> conflict-free ldmatrix).
// Stage: Ahi, Alo, Bhi tiles of 128 rows x 64B data each.
#define TILE_B 10240            // 128 * 80
#define STAGE_B (3 * TILE_B)    // 30720
#define GEMM_SMEM (2 * STAGE_B) // 61440

template<int MODE>
__global__ __launch_bounds__(256, 2)
void gemm_mma(const float* __restrict__ b0,
              const float* __restrict__ b1,
              const float* __restrict__ b2,
              float* __restrict__ out)
{
    extern __shared__ char smc[];
    const uint32_t sb = smem_u32(smc);
    const int t    = threadIdx.x;
    const int w    = t >> 5;
    const int lane = t & 31;
    const int wm   = w & 3;          // m-warp: rows wm*32 .. +32
    const int wn   = w >> 2;         // n-warp: cols wn*64 .. +64
    const int m0   = blockIdx.x * 128;
    const int n0   = blockIdx.y * 128;
    const int widx = (MODE == 0) ? (int)blockIdx.z : 3;

    const __half* Ahi = (MODE == 0) ? g_xhi : g_ohi;
    const __half* Alo = (MODE == 0) ? g_xlo : g_olo;
    const __half* Bhi = g_whi + (size_t)widx * CC * CC;
    const float* bias = b0;
    if (MODE == 0) { if (blockIdx.z == 1) bias = b1; else if (blockIdx.z == 2) bias = b2; }

    float acc[2][8][4];
    unsigned hacc[2][8][2];
#pragma unroll
    for (int a = 0; a < 2; a++)
#pragma unroll
        for (int n = 0; n < 8; n++) {
#pragma unroll
            for (int k = 0; k < 4; k++) acc[a][n][k] = 0.f;
            hacc[a][n][0] = 0u; hacc[a][n][1] = 0u;
        }

    // ldmatrix per-lane offsets
    const uint32_t aoff = (uint32_t)((lane & 15) * 80 + (lane >> 4) * 16);
    const uint32_t boff = (uint32_t)(((lane & 7) + (lane >> 4) * 8) * 80 + ((lane >> 3) & 1) * 16);

    // copy roles: 3 tiles * 128 rows * 4 chunks = 1536 / 256 thr = 6 each
    auto issue = [&](int ch) {
        const int k0 = ch * 32;
        const uint32_t stage = sb + (ch & 1) * STAGE_B;
#pragma unroll
        for (int i = 0; i < 6; i++) {
            int id   = i * 256 + t;
            int tile = id >> 9;
            int idx  = id & 511;
            int r    = idx & 127;
            int c    = (idx >> 7) & 3;
            const __half* gp;
            int row;
            if (tile == 0)      { row = m0 + r; gp = Ahi; }
            else if (tile == 1) { row = m0 + r; gp = Alo; }
            else                { row = n0 + r; gp = Bhi; }
            cpasync16(stage + tile * TILE_B + (uint32_t)(r * 80 + c * 16),
                      gp + (size_t)row * CC + k0 + c * 8);
        }
        CP_COMMIT();
    };

    issue(0);
    for (int ch = 0; ch < 32; ch++) {
        if (ch + 1 < 32) { issue(ch + 1); CP_WAIT1(); }
        else             { CP_WAIT0(); }
        __syncthreads();

        const uint32_t stage = sb + (ch & 1) * STAGE_B;
#pragma unroll
        for (int s = 0; s < 2; s++) {      // two k16 steps within BK=32
            unsigned ahi[2][4], alo[2][4];
#pragma unroll
            for (int mt = 0; mt < 2; mt++) {
                uint32_t ra = stage + (uint32_t)((wm * 32 + mt * 16) * 80) + aoff + s * 32;
                ldsm4(ahi[mt], ra);
                ldsm4(alo[mt], ra + TILE_B);
            }
#pragma unroll
            for (int np = 0; np < 4; np++) {   // n8-pairs: covers n = np*16 .. +16
                unsigned bhi[4];
                uint32_t rb = stage + 2 * TILE_B
                            + (uint32_t)((wn * 64 + np * 16) * 80) + boff + s * 32;
                ldsm4(bhi, rb);
#pragma unroll
                for (int mt = 0; mt < 2; mt++) {
#pragma unroll
                    for (int nh = 0; nh < 2; nh++) {
                        mma16816_f32(acc[mt][np * 2 + nh], ahi[mt], &bhi[2 * nh]);
                        mma16816_f16(hacc[mt][np * 2 + nh], alo[mt], &bhi[2 * nh]);
                    }
                }
            }
        }
        __syncthreads();
    }

    // epilogue: d0,d1 -> row l/4, cols 2(l%4),+1 ; d2,d3 -> row+8 (same for hacc)
    float* dst = g_q;
    if (MODE == 0) { if (blockIdx.z == 1) dst = g_k; else if (blockIdx.z == 2) dst = g_v; }

#pragma unroll
    for (int mt = 0; mt < 2; mt++) {
#pragma unroll
        for (int nt = 0; nt < 8; nt++) {
            float* d = acc[mt][nt];
            const int col = n0 + wn * 64 + nt * 8 + 2 * (lane & 3);
            const float bv0 = bias[col], bv1 = bias[col + 1];
            const int r0 = m0 + wm * 32 + mt * 16 + (lane >> 2);
#pragma unroll
            for (int half = 0; half < 2; half++) {
                const int r = r0 + half * 8;
                float2 lo = __half22float2(*(__half2*)&hacc[mt][nt][half]);
                float2 v = make_float2(d[2 * half]     + lo.x + bv0,
                                       d[2 * half + 1] + lo.y + bv1);
                if (MODE == 0) {
                    const int bb  = r >> 12;
                    const int tok = r & (NN - 1);
                    const int h   = col >> 6;
                    const int dd  = col & 63;
                    *(float2*)&dst[(((size_t)bb * HH + h) * NN + tok) * DDIM + dd] = v;
                } else {
                    *(float2*)&out[(size_t)r * CC + col] = v;
                }
            }
        }
    }
}

// ---------------- Attention: one CTA per (b, h, blk) -------------------------
// Window blocks [blk-1, blk]; right block fully causal-masked. fp32 math.
// Epilogue writes split-fp16 directly to g_ohi/g_olo.
#define SQ_OFF  0
#define SKV_OFF 4160
#define SS_OFF  (4160 + 8704)
#define ATT_SMEM_FLOATS (4160 + 8704 + 8704)
#define ATT_SMEM_BYTES  (ATT_SMEM_FLOATS * 4)

__device__ __forceinline__ unsigned long long pk2(float x, float y) {
    unsigned long long r;
    asm("mov.b64 %0, {%1, %2};" : "=l"(r) : "f"(x), "f"(y));
    return r;
}
__device__ __forceinline__ void upk2(unsigned long long v, float& x, float& y) {
    asm("mov.b64 {%0, %1}, %2;" : "=f"(x), "=f"(y) : "l"(v));
}
__device__ __forceinline__ unsigned long long ffma2(unsigned long long a,
                                                    unsigned long long b,
                                                    unsigned long long c) {
    unsigned long long d;
    asm("fma.rn.f32x2 %0, %1, %2, %3;" : "=l"(d) : "l"(a), "l"(b), "l"(c));
    return d;
}

__global__ __launch_bounds__(256)
void attn_kernel()
{
    extern __shared__ float sm[];
    float* sQ  = sm + SQ_OFF;
    float* sKV = sm + SKV_OFF;
    float* sS  = sm + SS_OFF;

    const int blk = blockIdx.x;
    const int h   = blockIdx.y;
    const int b   = blockIdx.z;
    const int t   = threadIdx.x;

    const size_t base = ((size_t)(b * HH + h)) * NN * DDIM;

#pragma unroll
    for (int s = t; s < 1024; s += 256) {
        int i  = s >> 4;
        int k4 = (s & 15) << 2;
        float4 v = *(const float4*)&g_q[base + (size_t)(blk * BSZ + i) * DDIM + k4];
        sQ[(k4 + 0) * 65 + i] = v.x;
        sQ[(k4 + 1) * 65 + i] = v.y;
        sQ[(k4 + 2) * 65 + i] = v.z;
        sQ[(k4 + 3) * 65 + i] = v.w;
    }
#pragma unroll
    for (int s = t; s < 2048; s += 256) {
        int j  = s >> 4;
        int k4 = (s & 15) << 2;
        int tokrel = (blk - 1) * BSZ + j;
        if (tokrel >= 0) {
            float4 v = *(const float4*)&g_k[base + (size_t)tokrel * DDIM + k4];
            sKV[(k4 + 0) * 136 + j] = v.x;
            sKV[(k4 + 1) * 136 + j] = v.y;
            sKV[(k4 + 2) * 136 + j] = v.z;
            sKV[(k4 + 3) * 136 + j] = v.w;
        }
    }
    __syncthreads();

    const int tx = t & 15, ty = t >> 4;
    const int i0 = ty * 4, j0 = tx * 8;

    unsigned long long sacc[4][4];
#pragma unroll
    for (int ii = 0; ii < 4; ii++)
#pragma unroll
        for (int jj = 0; jj < 4; jj++) sacc[ii][jj] = 0ull;

#pragma unroll 8
    for (int kk = 0; kk < 64; kk++) {
        unsigned long long bv[4];
#pragma unroll
        for (int jj = 0; jj < 4; jj++) {
            float2 f = *(const float2*)&sKV[kk * 136 + j0 + 2 * jj];
            bv[jj] = pk2(f.x, f.y);
        }
#pragma unroll
        for (int ii = 0; ii < 4; ii++) {
            float a = sQ[kk * 65 + i0 + ii];
            unsigned long long ap = pk2(a, a);
#pragma unroll
            for (int jj = 0; jj < 4; jj++)
                sacc[ii][jj] = ffma2(ap, bv[jj], sacc[ii][jj]);
        }
    }

    float sc[4][8];
#pragma unroll
    for (int ii = 0; ii < 4; ii++) {
        const int i = i0 + ii;
#pragma unroll
        for (int jj = 0; jj < 4; jj++) {
            float x0, x1;
            upk2(sacc[ii][jj], x0, x1);
            int j = j0 + 2 * jj;
            bool v0 = (j     <= 64 + i) && (j     >= 64 || blk > 0);
            bool v1 = (j + 1 <= 64 + i) && (j + 1 >= 64 || blk > 0);
            sc[ii][2 * jj]     = v0 ? x0 * 0.125f : -1e30f;
            sc[ii][2 * jj + 1] = v1 ? x1 * 0.125f : -1e30f;
        }
    }

    float mx[4];
#pragma unroll
    for (int ii = 0; ii < 4; ii++) {
        float m = sc[ii][0];
#pragma unroll
        for (int jj = 1; jj < 8; jj++) m = fmaxf(m, sc[ii][jj]);
        mx[ii] = m;
    }
#pragma unroll
    for (int off = 8; off >= 1; off >>= 1)
#pragma unroll
        for (int ii = 0; ii < 4; ii++)
            mx[ii] = fmaxf(mx[ii], __shfl_xor_sync(0xffffffffu, mx[ii], off));

    float sum[4];
#pragma unroll
    for (int ii = 0; ii < 4; ii++) {
        float s = 0.f;
#pragma unroll
        for (int jj = 0; jj < 8; jj++) {
            float e = __expf(sc[ii][jj] - mx[ii]);
            sc[ii][jj] = e;
            s += e;
        }
        sum[ii] = s;
    }
#pragma unroll
    for (int off = 8; off >= 1; off >>= 1)
#pragma unroll
        for (int ii = 0; ii < 4; ii++)
            sum[ii] += __shfl_xor_sync(0xffffffffu, sum[ii], off);

#pragma unroll
    for (int ii = 0; ii < 4; ii++) {
        float inv = 1.f / sum[ii];
#pragma unroll
        for (int jj = 0; jj < 8; jj++)
            sS[(i0 + ii) * 136 + j0 + jj] = sc[ii][jj] * inv;
    }
    __syncthreads();

#pragma unroll
    for (int s = t; s < 2048; s += 256) {
        int j   = s >> 4;
        int dd0 = (s & 15) << 2;
        int tokrel = (blk - 1) * BSZ + j;
        float4 v = make_float4(0.f, 0.f, 0.f, 0.f);
        if (tokrel >= 0)
            v = *(const float4*)&g_v[base + (size_t)tokrel * DDIM + dd0];
        *(float4*)&sKV[j * 68 + dd0] = v;
    }
    __syncthreads();

    const int dd0 = tx * 4;
    unsigned long long oa[4][2];
#pragma unroll
    for (int ii = 0; ii < 4; ii++) { oa[ii][0] = 0ull; oa[ii][1] = 0ull; }

#pragma unroll 8
    for (int j = 0; j < 128; j++) {
        float2 v0 = *(const float2*)&sKV[j * 68 + dd0];
        float2 v1 = *(const float2*)&sKV[j * 68 + dd0 + 2];
        unsigned long long bv0 = pk2(v0.x, v0.y);
        unsigned long long bv1 = pk2(v1.x, v1.y);
#pragma unroll
        for (int ii = 0; ii < 4; ii++) {
            float p = sS[(i0 + ii) * 136 + j];
            unsigned long long pp = pk2(p, p);
            oa[ii][0] = ffma2(pp, bv0, oa[ii][0]);
            oa[ii][1] = ffma2(pp, bv1, oa[ii][1]);
        }
    }

    // epilogue: write split-fp16 directly (input for O-projection GEMM)
#pragma unroll
    for (int ii = 0; ii < 4; ii++) {
        const int tok = blk * BSZ + i0 + ii;
        float o0, o1, o2, o3;
        upk2(oa[ii][0], o0, o1);
        upk2(oa[ii][1], o2, o3);
        __half h0 = __float2half_rn(o0);
        __half h1 = __float2half_rn(o1);
        __half h2 = __float2half_rn(o2);
        __half h3 = __float2half_rn(o3);
        size_t off = ((size_t)(b * NN) + tok) * CC + h * DDIM + dd0;
        __half2 p0; p0.x = h0; p0.y = h1;
        __half2 p1; p1.x = h2; p1.y = h3;
        *(__half2*)&g_ohi[off]     = p0;
        *(__half2*)&g_ohi[off + 2] = p1;
        __half2 l0 = __floats2half2_rn(o0 - __half2float(h0),
                                       o1 - __half2float(h1));
        __half2 l1 = __floats2half2_rn(o2 - __half2float(h2),
                                       o3 - __half2float(h3));
        *(__half2*)&g_olo[off]     = l0;
        *(__half2*)&g_olo[off + 2] = l1;
    }
}

// ---------------- launch ------------------------------------------------------
extern "C" void kernel_launch(void* const* d_in, const int* in_sizes, int n_in,
                              void* d_out, int out_size)
{
    const float* x  = (const float*)d_in[0];
    const float* Wq = (const float*)d_in[1];
    const float* bq = (const float*)d_in[2];
    const float* Wk = (const float*)d_in[3];
    const float* bk = (const float*)d_in[4];
    const float* Wv = (const float*)d_in[5];
    const float* bv = (const float*)d_in[6];
    const float* Wo = (const float*)d_in[7];
    const float* bo = (const float*)d_in[8];
    float* out = (float*)d_out;

    cudaFuncSetAttribute(attn_kernel,
                         cudaFuncAttributeMaxDynamicSharedMemorySize, ATT_SMEM_BYTES);
    cudaFuncSetAttribute(gemm_mma<0>,
                         cudaFuncAttributeMaxDynamicSharedMemorySize, GEMM_SMEM);
    cudaFuncSetAttribute(gemm_mma<1>,
                         cudaFuncAttributeMaxDynamicSharedMemorySize, GEMM_SMEM);

    // split fp32 -> fp16
    {
        int n4 = MTOT * CC / 4;
        convert_kernel<<<(n4 + 255) / 256, 256>>>(x, 0, n4);
        int w4 = CC * CC / 4;
        convert_kernel<<<(w4 + 255) / 256, 256>>>(Wq, 1, w4);
        convert_kernel<<<(w4 + 255) / 256, 256>>>(Wk, 2, w4);
        convert_kernel<<<(w4 + 255) / 256, 256>>>(Wv, 3, w4);
        convert_kernel<<<(w4 + 255) / 256, 256>>>(Wo, 4, w4);
    }

    // QKV projections on tensor cores (HMMA, split-fp16 2-product)
    dim3 g1(MTOT / 128, CC / 128, 3);
    gemm_mma<0><<<g1, 256, GEMM_SMEM>>>(bq, bk, bv, nullptr);

    // block-sparse attention (fp32), writes split-fp16 output
    attn_kernel<<<dim3(NBLK, HH, BB), 256, ATT_SMEM_BYTES>>>();

    // output projection on tensor cores
    dim3 g2(MTOT / 128, CC / 128, 1);
    gemm_mma<1><<<g2, 256, GEMM_SMEM>>>(bo, nullptr, nullptr, out);
}

// round 7
// speedup vs baseline: 2.4785x; 1.1354x over previous
#include <cuda_runtime.h>
#include <cuda_fp16.h>
#include <math.h>
#include <stdint.h>

// Problem constants
#define BB   4
#define NN   4096
#define CC   1024
#define HH   16
#define DDIM 64
#define BSZ  64
#define NBLK 64
#define MTOT (BB*NN)   // 16384

// ---------------- scratch (device globals, allocation-free) ------------------
__device__ __half g_xhi[(size_t)MTOT*CC];   // split-fp16 activations
__device__ __half g_xlo[(size_t)MTOT*CC];
__device__ __half g_whi[(size_t)4*CC*CC];   // Wq,Wk,Wv,Wo hi only (fp16)
__device__ __half g_qh[(size_t)BB*HH*NN*DDIM];  // q/k/v split-fp16 [b][h][n][d]
__device__ __half g_ql[(size_t)BB*HH*NN*DDIM];
__device__ __half g_kh[(size_t)BB*HH*NN*DDIM];
__device__ __half g_kl[(size_t)BB*HH*NN*DDIM];
__device__ __half g_vh[(size_t)BB*HH*NN*DDIM];
__device__ __half g_vl[(size_t)BB*HH*NN*DDIM];
__device__ __half g_ohi[(size_t)MTOT*CC];   // attention out split [m][c]
__device__ __half g_olo[(size_t)MTOT*CC];

// ---------------- PTX helpers (base sm_103 target only) ----------------------
__device__ __forceinline__ uint32_t smem_u32(const void* p) {
    uint32_t a;
    asm("{ .reg .u64 t; cvta.to.shared.u64 t, %1; cvt.u32.u64 %0, t; }"
        : "=r"(a) : "l"(p));
    return a;
}
__device__ __forceinline__ void ldsm4(unsigned* r, uint32_t addr) {
    asm volatile("ldmatrix.sync.aligned.m8n8.x4.shared.b16 {%0,%1,%2,%3}, [%4];"
                 : "=r"(r[0]), "=r"(r[1]), "=r"(r[2]), "=r"(r[3]) : "r"(addr));
}
__device__ __forceinline__ void ldsm4t(unsigned* r, uint32_t addr) {
    asm volatile("ldmatrix.sync.aligned.m8n8.x4.trans.shared.b16 {%0,%1,%2,%3}, [%4];"
                 : "=r"(r[0]), "=r"(r[1]), "=r"(r[2]), "=r"(r[3]) : "r"(addr));
}
__device__ __forceinline__ void mma16816_f32(float* d, const unsigned* a, const unsigned* b) {
    asm volatile(
        "mma.sync.aligned.m16n8k16.row.col.f32.f16.f16.f32 "
        "{%0,%1,%2,%3}, {%4,%5,%6,%7}, {%8,%9}, {%0,%1,%2,%3};"
        : "+f"(d[0]), "+f"(d[1]), "+f"(d[2]), "+f"(d[3])
        : "r"(a[0]), "r"(a[1]), "r"(a[2]), "r"(a[3]), "r"(b[0]), "r"(b[1]));
}
__device__ __forceinline__ void mma16816_f16(unsigned* d, const unsigned* a, const unsigned* b) {
    asm volatile(
        "mma.sync.aligned.m16n8k16.row.col.f16.f16.f16.f16 "
        "{%0,%1}, {%2,%3,%4,%5}, {%6,%7}, {%0,%1};"
        : "+r"(d[0]), "+r"(d[1])
        : "r"(a[0]), "r"(a[1]), "r"(a[2]), "r"(a[3]), "r"(b[0]), "r"(b[1]));
}
__device__ __forceinline__ void cpasync16(uint32_t saddr, const void* g) {
    asm volatile("cp.async.cg.shared.global [%0], [%1], 16;" :: "r"(saddr), "l"(g));
}
#define CP_COMMIT()  asm volatile("cp.async.commit_group;" ::: "memory")
#define CP_WAIT1()   asm volatile("cp.async.wait_group 1;" ::: "memory")
#define CP_WAIT0()   asm volatile("cp.async.wait_group 0;" ::: "memory")

// ---------------- split-fp32 -> fp16 conversion ------------------------------
__global__ void convert_kernel(const float* __restrict__ src, int sel, int n4)
{
    int i = blockIdx.x * blockDim.x + threadIdx.x;
    if (i >= n4) return;
    float4 v = ((const float4*)src)[i];
    __half h0 = __float2half_rn(v.x);
    __half h1 = __float2half_rn(v.y);
    __half h2 = __float2half_rn(v.z);
    __half h3 = __float2half_rn(v.w);
    __half2 ph0; ph0.x = h0; ph0.y = h1;
    __half2 ph1; ph1.x = h2; ph1.y = h3;
    if (sel == 0) {
        ((__half2*)g_xhi)[i * 2]     = ph0;
        ((__half2*)g_xhi)[i * 2 + 1] = ph1;
        __half2 pl0 = __floats2half2_rn(v.x - __half2float(h0),
                                        v.y - __half2float(h1));
        __half2 pl1 = __floats2half2_rn(v.z - __half2float(h2),
                                        v.w - __half2float(h3));
        ((__half2*)g_xlo)[i * 2]     = pl0;
        ((__half2*)g_xlo)[i * 2 + 1] = pl1;
    } else {
        __half* hi = g_whi + (size_t)(sel - 1) * CC * CC;
        ((__half2*)hi)[i * 2]     = ph0;
        ((__half2*)hi)[i * 2 + 1] = ph1;
    }
}

// ---------------- HMMA split-fp16 GEMM ---------------------------------------
// OUT[m][c] = sum_k X[m][k]*W[c][k] + bias[c]; CTA tile 128x128, BK=32.
// Products: Ahi*Bhi (fp32 acc) + Alo*Bhi (fp16 acc).
#define TILE_B 10240            // 128 * 80
#define STAGE_B (3 * TILE_B)    // 30720
#define GEMM_SMEM (2 * STAGE_B) // 61440

template<int MODE>
__global__ __launch_bounds__(256, 2)
void gemm_mma(const float* __restrict__ b0,
              const float* __restrict__ b1,
              const float* __restrict__ b2,
              float* __restrict__ out)
{
    extern __shared__ char smc[];
    const uint32_t sb = smem_u32(smc);
    const int t    = threadIdx.x;
    const int w    = t >> 5;
    const int lane = t & 31;
    const int wm   = w & 3;
    const int wn   = w >> 2;
    const int m0   = blockIdx.x * 128;
    const int n0   = blockIdx.y * 128;
    const int widx = (MODE == 0) ? (int)blockIdx.z : 3;

    const __half* Ahi = (MODE == 0) ? g_xhi : g_ohi;
    const __half* Alo = (MODE == 0) ? g_xlo : g_olo;
    const __half* Bhi = g_whi + (size_t)widx * CC * CC;
    const float* bias = b0;
    if (MODE == 0) { if (blockIdx.z == 1) bias = b1; else if (blockIdx.z == 2) bias = b2; }

    float acc[2][8][4];
    unsigned hacc[2][8][2];
#pragma unroll
    for (int a = 0; a < 2; a++)
#pragma unroll
        for (int n = 0; n < 8; n++) {
#pragma unroll
            for (int k = 0; k < 4; k++) acc[a][n][k] = 0.f;
            hacc[a][n][0] = 0u; hacc[a][n][1] = 0u;
        }

    const uint32_t aoff = (uint32_t)((lane & 15) * 80 + (lane >> 4) * 16);
    const uint32_t boff = (uint32_t)(((lane & 7) + (lane >> 4) * 8) * 80 + ((lane >> 3) & 1) * 16);

    auto issue = [&](int ch) {
        const int k0 = ch * 32;
        const uint32_t stage = sb + (ch & 1) * STAGE_B;
#pragma unroll
        for (int i = 0; i < 6; i++) {
            int id   = i * 256 + t;
            int tile = id >> 9;
            int idx  = id & 511;
            int r    = idx & 127;
            int c    = (idx >> 7) & 3;
            const __half* gp;
            int row;
            if (tile == 0)      { row = m0 + r; gp = Ahi; }
            else if (tile == 1) { row = m0 + r; gp = Alo; }
            else                { row = n0 + r; gp = Bhi; }
            cpasync16(stage + tile * TILE_B + (uint32_t)(r * 80 + c * 16),
                      gp + (size_t)row * CC + k0 + c * 8);
        }
        CP_COMMIT();
    };

    issue(0);
    for (int ch = 0; ch < 32; ch++) {
        if (ch + 1 < 32) { issue(ch + 1); CP_WAIT1(); }
        else             { CP_WAIT0(); }
        __syncthreads();

        const uint32_t stage = sb + (ch & 1) * STAGE_B;
#pragma unroll
        for (int s = 0; s < 2; s++) {
            unsigned ahi[2][4], alo[2][4];
#pragma unroll
            for (int mt = 0; mt < 2; mt++) {
                uint32_t ra = stage + (uint32_t)((wm * 32 + mt * 16) * 80) + aoff + s * 32;
                ldsm4(ahi[mt], ra);
                ldsm4(alo[mt], ra + TILE_B);
            }
#pragma unroll
            for (int np = 0; np < 4; np++) {
                unsigned bhi[4];
                uint32_t rb = stage + 2 * TILE_B
                            + (uint32_t)((wn * 64 + np * 16) * 80) + boff + s * 32;
                ldsm4(bhi, rb);
#pragma unroll
                for (int mt = 0; mt < 2; mt++) {
#pragma unroll
                    for (int nh = 0; nh < 2; nh++) {
                        mma16816_f32(acc[mt][np * 2 + nh], ahi[mt], &bhi[2 * nh]);
                        mma16816_f16(hacc[mt][np * 2 + nh], alo[mt], &bhi[2 * nh]);
                    }
                }
            }
        }
        __syncthreads();
    }

    // epilogue
    __half* dsthi = g_qh;
    __half* dstlo = g_ql;
    if (MODE == 0) {
        if (blockIdx.z == 1)      { dsthi = g_kh; dstlo = g_kl; }
        else if (blockIdx.z == 2) { dsthi = g_vh; dstlo = g_vl; }
    }

#pragma unroll
    for (int mt = 0; mt < 2; mt++) {
#pragma unroll
        for (int nt = 0; nt < 8; nt++) {
            float* d = acc[mt][nt];
            const int col = n0 + wn * 64 + nt * 8 + 2 * (lane & 3);
            const float bv0 = bias[col], bv1 = bias[col + 1];
            const int r0 = m0 + wm * 32 + mt * 16 + (lane >> 2);
#pragma unroll
            for (int half = 0; half < 2; half++) {
                const int r = r0 + half * 8;
                float2 lo = __half22float2(*(__half2*)&hacc[mt][nt][half]);
                float2 v = make_float2(d[2 * half]     + lo.x + bv0,
                                       d[2 * half + 1] + lo.y + bv1);
                if (MODE == 0) {
                    const int bb  = r >> 12;
                    const int tok = r & (NN - 1);
                    const int h   = col >> 6;
                    const int dd  = col & 63;
                    __half2 hv = __floats2half2_rn(v.x, v.y);
                    float2 hf = __half22float2(hv);
                    __half2 lv = __floats2half2_rn(v.x - hf.x, v.y - hf.y);
                    size_t o = (((size_t)bb * HH + h) * NN + tok) * DDIM + dd;
                    *(__half2*)&dsthi[o] = hv;
                    *(__half2*)&dstlo[o] = lv;
                } else {
                    *(float2*)&out[(size_t)r * CC + col] = v;
                }
            }
        }
    }
}

// ---------------- Attention on HMMA: one CTA (128 thr) per (b, h, blk) -------
// Window = blocks [blk-1, blk] (right block fully causal-masked). 3-product
// split-fp16 MMA (error ~2^-22): qk = qh*kh + qh*kl + ql*kh; pv similarly.
// smem rows padded to 144B (9 x 16B; gcd(9,8)=1 -> conflict-free ldmatrix).
#define AQH 0
#define AQL 9216
#define AKH 18432
#define AKL 36864
#define AVH 55296
#define AVL 73728
#define ATT_SMEM 92160

__global__ __launch_bounds__(128, 2)
void attn_mma()
{
    extern __shared__ char smc[];
    const uint32_t sb = smem_u32(smc);
    const int blk = blockIdx.x;
    const int hd  = blockIdx.y;
    const int b   = blockIdx.z;
    const int t   = threadIdx.x;
    const int w   = t >> 5;
    const int lane = t & 31;

    const size_t base = ((size_t)(b * HH + hd)) * NN * DDIM;

    // load Q (64x64): 512 16B-chunks / 128 thr = 4 each (hi+lo)
#pragma unroll
    for (int i = 0; i < 4; i++) {
        int id = i * 128 + t;
        int r = id >> 3, c = id & 7;
        size_t o = base + (size_t)(blk * BSZ + r) * DDIM;
        *(uint4*)(smc + AQH + r * 144 + c * 16) = *((const uint4*)(g_qh + o) + c);
        *(uint4*)(smc + AQL + r * 144 + c * 16) = *((const uint4*)(g_ql + o) + c);
    }
    // load K,V window (128x64 each): 1024 chunks / 128 thr = 8 each
#pragma unroll
    for (int i = 0; i < 8; i++) {
        int id = i * 128 + t;
        int r = id >> 3, c = id & 7;
        int tokrel = (blk - 1) * BSZ + r;
        uint4 z = make_uint4(0u, 0u, 0u, 0u);
        uint4 kh = z, kl = z, vh = z, vl = z;
        if (tokrel >= 0) {
            size_t o = base + (size_t)tokrel * DDIM;
            kh = *((const uint4*)(g_kh + o) + c);
            kl = *((const uint4*)(g_kl + o) + c);
            vh = *((const uint4*)(g_vh + o) + c);
            vl = *((const uint4*)(g_vl + o) + c);
        }
        *(uint4*)(smc + AKH + r * 144 + c * 16) = kh;
        *(uint4*)(smc + AKL + r * 144 + c * 16) = kl;
        *(uint4*)(smc + AVH + r * 144 + c * 16) = vh;
        *(uint4*)(smc + AVL + r * 144 + c * 16) = vl;
    }
    __syncthreads();

    // ---- QK^T: warp w owns rows mw..mw+16; 16 n8 score tiles over 128 cols --
    const int mw = w * 16;
    float sc[16][4];
#pragma unroll
    for (int j = 0; j < 16; j++)
#pragma unroll
        for (int k = 0; k < 4; k++) sc[j][k] = 0.f;

    const uint32_t aoffQ = (uint32_t)((mw + (lane & 15)) * 144 + (lane >> 4) * 16);
    const uint32_t boffK = (uint32_t)(((lane & 7) + (lane >> 4) * 8) * 144 + ((lane >> 3) & 1) * 16);

#pragma unroll
    for (int s = 0; s < 4; s++) {          // 4 k16 steps over d=64
        unsigned aq[4], al[4];
        ldsm4(aq, sb + AQH + aoffQ + s * 32);
        ldsm4(al, sb + AQL + aoffQ + s * 32);
#pragma unroll
        for (int g = 0; g < 8; g++) {      // n16 groups over 128 tokens
            unsigned bh[4], bl[4];
            uint32_t ka = sb + AKH + boffK + (uint32_t)(g * 16 * 144) + s * 32;
            ldsm4(bh, ka);
            ldsm4(bl, ka + (AKL - AKH));
#pragma unroll
            for (int nh = 0; nh < 2; nh++) {
                float* d = sc[g * 2 + nh];
                mma16816_f32(d, aq, &bh[2 * nh]);
                mma16816_f32(d, aq, &bl[2 * nh]);
                mma16816_f32(d, al, &bh[2 * nh]);
            }
        }
    }

    // ---- mask + scale + softmax (rows on 4-lane quads) ----------------------
    const int ilow = mw + (lane >> 2);         // rows for d0,d1 (d2,d3: +8)
    const int c00  = 2 * (lane & 3);
    float mx0 = -1e30f, mx1 = -1e30f;
#pragma unroll
    for (int j = 0; j < 16; j++) {
        int c0 = j * 8 + c00;
        bool kv0 = (c0     >= 64) || (blk > 0);
        bool kv1 = (c0 + 1 >= 64) || (blk > 0);
        bool v0a = (c0     <= 64 + ilow) && kv0;
        bool v1a = (c0 + 1 <= 64 + ilow) && kv1;
        bool v0b = (c0     <= 72 + ilow) && kv0;
        bool v1b = (c0 + 1 <= 72 + ilow) && kv1;
        sc[j][0] = v0a ? sc[j][0] * 0.125f : -1e30f;
        sc[j][1] = v1a ? sc[j][1] * 0.125f : -1e30f;
        sc[j][2] = v0b ? sc[j][2] * 0.125f : -1e30f;
        sc[j][3] = v1b ? sc[j][3] * 0.125f : -1e30f;
        mx0 = fmaxf(mx0, fmaxf(sc[j][0], sc[j][1]));
        mx1 = fmaxf(mx1, fmaxf(sc[j][2], sc[j][3]));
    }
    mx0 = fmaxf(mx0, __shfl_xor_sync(0xffffffffu, mx0, 1));
    mx0 = fmaxf(mx0, __shfl_xor_sync(0xffffffffu, mx0, 2));
    mx1 = fmaxf(mx1, __shfl_xor_sync(0xffffffffu, mx1, 1));
    mx1 = fmaxf(mx1, __shfl_xor_sync(0xffffffffu, mx1, 2));

    float sm0 = 0.f, sm1 = 0.f;
#pragma unroll
    for (int j = 0; j < 16; j++) {
        sc[j][0] = __expf(sc[j][0] - mx0);
        sc[j][1] = __expf(sc[j][1] - mx0);
        sc[j][2] = __expf(sc[j][2] - mx1);
        sc[j][3] = __expf(sc[j][3] - mx1);
        sm0 += sc[j][0] + sc[j][1];
        sm1 += sc[j][2] + sc[j][3];
    }
    sm0 += __shfl_xor_sync(0xffffffffu, sm0, 1);
    sm0 += __shfl_xor_sync(0xffffffffu, sm0, 2);
    sm1 += __shfl_xor_sync(0xffffffffu, sm1, 1);
    sm1 += __shfl_xor_sync(0xffffffffu, sm1, 2);
    const float inv0 = 1.f / sm0, inv1 = 1.f / sm1;

    // ---- P -> split-fp16 A-fragments (D-frag == A-frag identity) ------------
    unsigned pa[8][4], pl[8][4];
#pragma unroll
    for (int j = 0; j < 8; j++) {
#pragma unroll
        for (int half = 0; half < 2; half++) {   // tiles 2j, 2j+1
            float p0 = sc[2 * j + half][0] * inv0;
            float p1 = sc[2 * j + half][1] * inv0;
            float p2 = sc[2 * j + half][2] * inv1;
            float p3 = sc[2 * j + half][3] * inv1;
            __half2 h01 = __floats2half2_rn(p0, p1);
            __half2 h23 = __floats2half2_rn(p2, p3);
            float2 f01 = __half22float2(h01);
            float2 f23 = __half22float2(h23);
            __half2 l01 = __floats2half2_rn(p0 - f01.x, p1 - f01.y);
            __half2 l23 = __floats2half2_rn(p2 - f23.x, p3 - f23.y);
            pa[j][2 * half]     = *(unsigned*)&h01;
            pa[j][2 * half + 1] = *(unsigned*)&h23;
            pl[j][2 * half]     = *(unsigned*)&l01;
            pl[j][2 * half + 1] = *(unsigned*)&l23;
        }
    }

    // ---- PV: O(16x64) per warp; V via ldmatrix.trans ------------------------
    float oac[8][4];
#pragma unroll
    for (int n = 0; n < 8; n++)
#pragma unroll
        for (int k = 0; k < 4; k++) oac[n][k] = 0.f;

#pragma unroll
    for (int j = 0; j < 8; j++) {              // k16 over 128 tokens
#pragma unroll
        for (int g = 0; g < 4; g++) {          // n16 over d=64
            unsigned bh[4], bl[4];
            uint32_t va = sb + AVH
                        + (uint32_t)((j * 16 + (lane & 15)) * 144)
                        + (uint32_t)((g * 16 + (lane >> 4) * 8) * 2);
            ldsm4t(bh, va);
            ldsm4t(bl, va + (AVL - AVH));
#pragma unroll
            for (int nh = 0; nh < 2; nh++) {
                float* d = oac[g * 2 + nh];
                mma16816_f32(d, pa[j], &bh[2 * nh]);
                mma16816_f32(d, pa[j], &bl[2 * nh]);
                mma16816_f32(d, pl[j], &bh[2 * nh]);
            }
        }
    }

    // ---- epilogue: write split-fp16 O [m][c] for the O-projection ----------
#pragma unroll
    for (int nt = 0; nt < 8; nt++) {
        float* d = oac[nt];
        const int dd = nt * 8 + c00;
#pragma unroll
        for (int half = 0; half < 2; half++) {
            const int tok = blk * BSZ + ilow + half * 8;
            float o0 = d[2 * half], o1 = d[2 * half + 1];
            __half2 hv = __floats2half2_rn(o0, o1);
            float2 hf = __half22float2(hv);
            __half2 lv = __floats2half2_rn(o0 - hf.x, o1 - hf.y);
            size_t o = ((size_t)(b * NN) + tok) * CC + hd * DDIM + dd;
            *(__half2*)&g_ohi[o] = hv;
            *(__half2*)&g_olo[o] = lv;
        }
    }
}

// ---------------- launch ------------------------------------------------------
extern "C" void kernel_launch(void* const* d_in, const int* in_sizes, int n_in,
                              void* d_out, int out_size)
{
    const float* x  = (const float*)d_in[0];
    const float* Wq = (const float*)d_in[1];
    const float* bq = (const float*)d_in[2];
    const float* Wk = (const float*)d_in[3];
    const float* bk = (const float*)d_in[4];
    const float* Wv = (const float*)d_in[5];
    const float* bv = (const float*)d_in[6];
    const float* Wo = (const float*)d_in[7];
    const float* bo = (const float*)d_in[8];
    float* out = (float*)d_out;

    cudaFuncSetAttribute(attn_mma,
                         cudaFuncAttributeMaxDynamicSharedMemorySize, ATT_SMEM);
    cudaFuncSetAttribute(gemm_mma<0>,
                         cudaFuncAttributeMaxDynamicSharedMemorySize, GEMM_SMEM);
    cudaFuncSetAttribute(gemm_mma<1>,
                         cudaFuncAttributeMaxDynamicSharedMemorySize, GEMM_SMEM);

    // split fp32 -> fp16
    {
        int n4 = MTOT * CC / 4;
        convert_kernel<<<(n4 + 255) / 256, 256>>>(x, 0, n4);
        int w4 = CC * CC / 4;
        convert_kernel<<<(w4 + 255) / 256, 256>>>(Wq, 1, w4);
        convert_kernel<<<(w4 + 255) / 256, 256>>>(Wk, 2, w4);
        convert_kernel<<<(w4 + 255) / 256, 256>>>(Wv, 3, w4);
        convert_kernel<<<(w4 + 255) / 256, 256>>>(Wo, 4, w4);
    }

    // QKV projections (HMMA), epilogue writes split-fp16 q/k/v
    dim3 g1(MTOT / 128, CC / 128, 3);
    gemm_mma<0><<<g1, 256, GEMM_SMEM>>>(bq, bk, bv, nullptr);

    // block-sparse attention on HMMA (3-product, fp32-equivalent)
    attn_mma<<<dim3(NBLK, HH, BB), 128, ATT_SMEM>>>();

    // output projection
    dim3 g2(MTOT / 128, CC / 128, 1);
    gemm_mma<1><<<g2, 256, GEMM_SMEM>>>(bo, nullptr, nullptr, out);
}

// round 10
// speedup vs baseline: 2.5293x; 1.0205x over previous
#include <cuda_runtime.h>
#include <cuda_fp16.h>
#include <math.h>
#include <stdint.h>

// Problem constants
#define BB   4
#define NN   4096
#define CC   1024
#define HH   16
#define DDIM 64
#define BSZ  64
#define NBLK 64
#define MTOT (BB*NN)   // 16384

// ---------------- scratch (device globals, allocation-free) ------------------
__device__ __half g_xhi[(size_t)MTOT*CC];       // fp16(x)
__device__ __half g_whi[(size_t)4*CC*CC];       // Wq,Wk,Wv,Wo fp16
__device__ __half g_qh[(size_t)BB*HH*NN*DDIM];  // q/k/v split-fp16 [b][h][n][d]
__device__ __half g_ql[(size_t)BB*HH*NN*DDIM];
__device__ __half g_kh[(size_t)BB*HH*NN*DDIM];
__device__ __half g_kl[(size_t)BB*HH*NN*DDIM];
__device__ __half g_vh[(size_t)BB*HH*NN*DDIM];
__device__ __half g_vl[(size_t)BB*HH*NN*DDIM];
__device__ __half g_ohi[(size_t)MTOT*CC];       // attention out [m][c] (hi only)

// ---------------- PTX helpers (base sm_103 target only) ----------------------
__device__ __forceinline__ uint32_t smem_u32(const void* p) {
    uint32_t a;
    asm("{ .reg .u64 t; cvta.to.shared.u64 t, %1; cvt.u32.u64 %0, t; }"
        : "=r"(a) : "l"(p));
    return a;
}
__device__ __forceinline__ void ldsm4(unsigned* r, uint32_t addr) {
    asm volatile("ldmatrix.sync.aligned.m8n8.x4.shared.b16 {%0,%1,%2,%3}, [%4];"
                 : "=r"(r[0]), "=r"(r[1]), "=r"(r[2]), "=r"(r[3]) : "r"(addr));
}
__device__ __forceinline__ void ldsm4t(unsigned* r, uint32_t addr) {
    asm volatile("ldmatrix.sync.aligned.m8n8.x4.trans.shared.b16 {%0,%1,%2,%3}, [%4];"
                 : "=r"(r[0]), "=r"(r[1]), "=r"(r[2]), "=r"(r[3]) : "r"(addr));
}
__device__ __forceinline__ void mma16816_f32(float* d, const unsigned* a, const unsigned* b) {
    asm volatile(
        "mma.sync.aligned.m16n8k16.row.col.f32.f16.f16.f32 "
        "{%0,%1,%2,%3}, {%4,%5,%6,%7}, {%8,%9}, {%0,%1,%2,%3};"
        : "+f"(d[0]), "+f"(d[1]), "+f"(d[2]), "+f"(d[3])
        : "r"(a[0]), "r"(a[1]), "r"(a[2]), "r"(a[3]), "r"(b[0]), "r"(b[1]));
}
__device__ __forceinline__ void cpasync16(uint32_t saddr, const void* g) {
    asm volatile("cp.async.cg.shared.global [%0], [%1], 16;" :: "r"(saddr), "l"(g));
}
#define CP_COMMIT()  asm volatile("cp.async.commit_group;" ::: "memory")
#define CP_WAIT2()   asm volatile("cp.async.wait_group 2;" ::: "memory")
#define CP_WAIT0()   asm volatile("cp.async.wait_group 0;" ::: "memory")

// ---------------- fp32 -> fp16 conversion ------------------------------------
// sel 0: x -> g_xhi. sel 1..4: W -> g_whi[(sel-1)].
__global__ void convert_kernel(const float* __restrict__ src, int sel, int n4)
{
    int i = blockIdx.x * blockDim.x + threadIdx.x;
    if (i >= n4) return;
    float4 v = ((const float4*)src)[i];
    __half2 ph0 = __floats2half2_rn(v.x, v.y);
    __half2 ph1 = __floats2half2_rn(v.z, v.w);
    __half* hi = (sel == 0) ? g_xhi : (g_whi + (size_t)(sel - 1) * CC * CC);
    ((__half2*)hi)[i * 2]     = ph0;
    ((__half2*)hi)[i * 2 + 1] = ph1;
}

// ---------------- HMMA single-product GEMM -----------------------------------
// OUT[m][c] = sum_k Xhi[m][k]*Whi[c][k] + bias[c]; CTA tile 128x128, BK=32.
// smem rows padded to 80B (gcd(5,8)=1 -> conflict-free ldmatrix).
// 3-stage cp.async pipeline; stage = A + B tile (2 x 10240 B).
#define TILE_B 10240            // 128 * 80
#define STAGE_B (2 * TILE_B)    // 20480
#define GEMM_SMEM (3 * STAGE_B) // 61440

template<int MODE>
__global__ __launch_bounds__(256, 2)
void gemm_mma(const float* __restrict__ b0,
              const float* __restrict__ b1,
              const float* __restrict__ b2,
              float* __restrict__ out)
{
    extern __shared__ char smc[];
    const uint32_t sb = smem_u32(smc);
    const int t    = threadIdx.x;
    const int w    = t >> 5;
    const int lane = t & 31;
    const int wm   = w & 3;
    const int wn   = w >> 2;
    const int m0   = blockIdx.x * 128;
    const int n0   = blockIdx.y * 128;
    const int widx = (MODE == 0) ? (int)blockIdx.z : 3;

    const __half* Ahi = (MODE == 0) ? g_xhi : g_ohi;
    const __half* Bhi = g_whi + (size_t)widx * CC * CC;
    const float* bias = b0;
    if (MODE == 0) { if (blockIdx.z == 1) bias = b1; else if (blockIdx.z == 2) bias = b2; }

    float acc[2][8][4];
#pragma unroll
    for (int a = 0; a < 2; a++)
#pragma unroll
        for (int n = 0; n < 8; n++)
#pragma unroll
            for (int k = 0; k < 4; k++) acc[a][n][k] = 0.f;

    const uint32_t aoff = (uint32_t)((lane & 15) * 80 + (lane >> 4) * 16);
    const uint32_t boff = (uint32_t)(((lane & 7) + (lane >> 4) * 8) * 80 + ((lane >> 3) & 1) * 16);

    // copy roles: 2 tiles * 512 chunks = 1024 / 256 thr = 4 each
    auto issue = [&](int ch) {
        const int k0 = ch * 32;
        const uint32_t stage = sb + (uint32_t)((ch % 3) * STAGE_B);
#pragma unroll
        for (int i = 0; i < 4; i++) {
            int id   = i * 256 + t;
            int tile = id >> 9;
            int idx  = id & 511;
            int r    = idx & 127;
            int c    = (idx >> 7) & 3;
            const __half* gp = tile ? Bhi : Ahi;
            int row = (tile ? n0 : m0) + r;
            cpasync16(stage + (uint32_t)(tile * TILE_B + r * 80 + c * 16),
                      gp + (size_t)row * CC + k0 + c * 8);
        }
        CP_COMMIT();
    };

    issue(0);
    issue(1);
    for (int ch = 0; ch < 32; ch++) {
        if (ch + 2 < 32) issue(ch + 2);
        CP_WAIT2();              // group ch complete (<=2 younger pending)
        __syncthreads();

        const uint32_t stage = sb + (uint32_t)((ch % 3) * STAGE_B);
#pragma unroll
        for (int s = 0; s < 2; s++) {
            unsigned ahi[2][4];
#pragma unroll
            for (int mt = 0; mt < 2; mt++)
                ldsm4(ahi[mt], stage + (uint32_t)((wm * 32 + mt * 16) * 80) + aoff + s * 32);
#pragma unroll
            for (int np = 0; np < 4; np++) {
                unsigned bhi[4];
                ldsm4(bhi, stage + TILE_B
                           + (uint32_t)((wn * 64 + np * 16) * 80) + boff + s * 32);
#pragma unroll
                for (int mt = 0; mt < 2; mt++) {
#pragma unroll
                    for (int nh = 0; nh < 2; nh++)
                        mma16816_f32(acc[mt][np * 2 + nh], ahi[mt], &bhi[2 * nh]);
                }
            }
        }
        __syncthreads();
    }
    CP_WAIT0();

    // epilogue
    __half* dsthi = g_qh;
    __half* dstlo = g_ql;
    if (MODE == 0) {
        if (blockIdx.z == 1)      { dsthi = g_kh; dstlo = g_kl; }
        else if (blockIdx.z == 2) { dsthi = g_vh; dstlo = g_vl; }
    }

#pragma unroll
    for (int mt = 0; mt < 2; mt++) {
#pragma unroll
        for (int nt = 0; nt < 8; nt++) {
            float* d = acc[mt][nt];
            const int col = n0 + wn * 64 + nt * 8 + 2 * (lane & 3);
            const float bv0 = bias[col], bv1 = bias[col + 1];
            const int r0 = m0 + wm * 32 + mt * 16 + (lane >> 2);
#pragma unroll
            for (int half = 0; half < 2; half++) {
                const int r = r0 + half * 8;
                float2 v = make_float2(d[2 * half] + bv0, d[2 * half + 1] + bv1);
                if (MODE == 0) {
                    const int bb  = r >> 12;
                    const int tok = r & (NN - 1);
                    const int h   = col >> 6;
                    const int dd  = col & 63;
                    __half2 hv = __floats2half2_rn(v.x, v.y);
                    float2 hf = __half22float2(hv);
                    __half2 lv = __floats2half2_rn(v.x - hf.x, v.y - hf.y);
                    size_t o = (((size_t)bb * HH + h) * NN + tok) * DDIM + dd;
                    *(__half2*)&dsthi[o] = hv;
                    *(__half2*)&dstlo[o] = lv;
                } else {
                    *(float2*)&out[(size_t)r * CC + col] = v;
                }
            }
        }
    }
}

// ---------------- Attention on HMMA: one CTA (128 thr) per (b, h, blk) -------
// Window = blocks [blk-1, blk] (right block fully causal-masked). 3-product
// split-fp16 MMA (error ~2^-22): qk = qh*kh + qh*kl + ql*kh; pv similarly.
// smem rows padded to 144B (9 x 16B; gcd(9,8)=1 -> conflict-free ldmatrix).
#define AQH 0
#define AQL 9216
#define AKH 18432
#define AKL 36864
#define AVH 55296
#define AVL 73728
#define ATT_SMEM 92160

__global__ __launch_bounds__(128, 2)
void attn_mma()
{
    extern __shared__ char smc[];
    const uint32_t sb = smem_u32(smc);
    const int blk = blockIdx.x;
    const int hd  = blockIdx.y;
    const int b   = blockIdx.z;
    const int t   = threadIdx.x;
    const int w   = t >> 5;
    const int lane = t & 31;

    const size_t base = ((size_t)(b * HH + hd)) * NN * DDIM;

    // load Q (64x64): hi+lo
#pragma unroll
    for (int i = 0; i < 4; i++) {
        int id = i * 128 + t;
        int r = id >> 3, c = id & 7;
        size_t o = base + (size_t)(blk * BSZ + r) * DDIM;
        *(uint4*)(smc + AQH + r * 144 + c * 16) = *((const uint4*)(g_qh + o) + c);
        *(uint4*)(smc + AQL + r * 144 + c * 16) = *((const uint4*)(g_ql + o) + c);
    }
    // load K,V window (128x64 each): hi+lo
#pragma unroll
    for (int i = 0; i < 8; i++) {
        int id = i * 128 + t;
        int r = id >> 3, c = id & 7;
        int tokrel = (blk - 1) * BSZ + r;
        uint4 z = make_uint4(0u, 0u, 0u, 0u);
        uint4 kh = z, kl = z, vh = z, vl = z;
        if (tokrel >= 0) {
            size_t o = base + (size_t)tokrel * DDIM;
            kh = *((const uint4*)(g_kh + o) + c);
            kl = *((const uint4*)(g_kl + o) + c);
            vh = *((const uint4*)(g_vh + o) + c);
            vl = *((const uint4*)(g_vl + o) + c);
        }
        *(uint4*)(smc + AKH + r * 144 + c * 16) = kh;
        *(uint4*)(smc + AKL + r * 144 + c * 16) = kl;
        *(uint4*)(smc + AVH + r * 144 + c * 16) = vh;
        *(uint4*)(smc + AVL + r * 144 + c * 16) = vl;
    }
    __syncthreads();

    // ---- QK^T: warp w owns rows mw..mw+16 -----------------------------------
    const int mw = w * 16;
    float sc[16][4];
#pragma unroll
    for (int j = 0; j < 16; j++)
#pragma unroll
        for (int k = 0; k < 4; k++) sc[j][k] = 0.f;

    const uint32_t aoffQ = (uint32_t)((mw + (lane & 15)) * 144 + (lane >> 4) * 16);
    const uint32_t boffK = (uint32_t)(((lane & 7) + (lane >> 4) * 8) * 144 + ((lane >> 3) & 1) * 16);

#pragma unroll
    for (int s = 0; s < 4; s++) {
        unsigned aq[4], al[4];
        ldsm4(aq, sb + AQH + aoffQ + s * 32);
        ldsm4(al, sb + AQL + aoffQ + s * 32);
#pragma unroll
        for (int g = 0; g < 8; g++) {
            unsigned bh[4], bl[4];
            uint32_t ka = sb + AKH + boffK + (uint32_t)(g * 16 * 144) + s * 32;
            ldsm4(bh, ka);
            ldsm4(bl, ka + (AKL - AKH));
#pragma unroll
            for (int nh = 0; nh < 2; nh++) {
                float* d = sc[g * 2 + nh];
                mma16816_f32(d, aq, &bh[2 * nh]);
                mma16816_f32(d, aq, &bl[2 * nh]);
                mma16816_f32(d, al, &bh[2 * nh]);
            }
        }
    }

    // ---- mask + scale + softmax ---------------------------------------------
    const int ilow = mw + (lane >> 2);
    const int c00  = 2 * (lane & 3);
    float mx0 = -1e30f, mx1 = -1e30f;
#pragma unroll
    for (int j = 0; j < 16; j++) {
        int c0 = j * 8 + c00;
        bool kv0 = (c0     >= 64) || (blk > 0);
        bool kv1 = (c0 + 1 >= 64) || (blk > 0);
        bool v0a = (c0     <= 64 + ilow) && kv0;
        bool v1a = (c0 + 1 <= 64 + ilow) && kv1;
        bool v0b = (c0     <= 72 + ilow) && kv0;
        bool v1b = (c0 + 1 <= 72 + ilow) && kv1;
        sc[j][0] = v0a ? sc[j][0] * 0.125f : -1e30f;
        sc[j][1] = v1a ? sc[j][1] * 0.125f : -1e30f;
        sc[j][2] = v0b ? sc[j][2] * 0.125f : -1e30f;
        sc[j][3] = v1b ? sc[j][3] * 0.125f : -1e30f;
        mx0 = fmaxf(mx0, fmaxf(sc[j][0], sc[j][1]));
        mx1 = fmaxf(mx1, fmaxf(sc[j][2], sc[j][3]));
    }
    mx0 = fmaxf(mx0, __shfl_xor_sync(0xffffffffu, mx0, 1));
    mx0 = fmaxf(mx0, __shfl_xor_sync(0xffffffffu, mx0, 2));
    mx1 = fmaxf(mx1, __shfl_xor_sync(0xffffffffu, mx1, 1));
    mx1 = fmaxf(mx1, __shfl_xor_sync(0xffffffffu, mx1, 2));

    float sm0 = 0.f, sm1 = 0.f;
#pragma unroll
    for (int j = 0; j < 16; j++) {
        sc[j][0] = __expf(sc[j][0] - mx0);
        sc[j][1] = __expf(sc[j][1] - mx0);
        sc[j][2] = __expf(sc[j][2] - mx1);
        sc[j][3] = __expf(sc[j][3] - mx1);
        sm0 += sc[j][0] + sc[j][1];
        sm1 += sc[j][2] + sc[j][3];
    }
    sm0 += __shfl_xor_sync(0xffffffffu, sm0, 1);
    sm0 += __shfl_xor_sync(0xffffffffu, sm0, 2);
    sm1 += __shfl_xor_sync(0xffffffffu, sm1, 1);
    sm1 += __shfl_xor_sync(0xffffffffu, sm1, 2);
    const float inv0 = 1.f / sm0, inv1 = 1.f / sm1;

    // ---- P -> split-fp16 A-fragments ----------------------------------------
    unsigned pa[8][4], pl[8][4];
#pragma unroll
    for (int j = 0; j < 8; j++) {
#pragma unroll
        for (int half = 0; half < 2; half++) {
            float p0 = sc[2 * j + half][0] * inv0;
            float p1 = sc[2 * j + half][1] * inv0;
            float p2 = sc[2 * j + half][2] * inv1;
            float p3 = sc[2 * j + half][3] * inv1;
            __half2 h01 = __floats2half2_rn(p0, p1);
            __half2 h23 = __floats2half2_rn(p2, p3);
            float2 f01 = __half22float2(h01);
            float2 f23 = __half22float2(h23);
            __half2 l01 = __floats2half2_rn(p0 - f01.x, p1 - f01.y);
            __half2 l23 = __floats2half2_rn(p2 - f23.x, p3 - f23.y);
            pa[j][2 * half]     = *(unsigned*)&h01;
            pa[j][2 * half + 1] = *(unsigned*)&h23;
            pl[j][2 * half]     = *(unsigned*)&l01;
            pl[j][2 * half + 1] = *(unsigned*)&l23;
        }
    }

    // ---- PV -----------------------------------------------------------------
    float oac[8][4];
#pragma unroll
    for (int n = 0; n < 8; n++)
#pragma unroll
        for (int k = 0; k < 4; k++) oac[n][k] = 0.f;

#pragma unroll
    for (int j = 0; j < 8; j++) {
#pragma unroll
        for (int g = 0; g < 4; g++) {
            unsigned bh[4], bl[4];
            uint32_t va = sb + AVH
                        + (uint32_t)((j * 16 + (lane & 15)) * 144)
                        + (uint32_t)((g * 16 + (lane >> 4) * 8) * 2);
            ldsm4t(bh, va);
            ldsm4t(bl, va + (AVL - AVH));
#pragma unroll
            for (int nh = 0; nh < 2; nh++) {
                float* d = oac[g * 2 + nh];
                mma16816_f32(d, pa[j], &bh[2 * nh]);
                mma16816_f32(d, pa[j], &bl[2 * nh]);
                mma16816_f32(d, pl[j], &bh[2 * nh]);
            }
        }
    }

    // ---- epilogue: hi only (O-projection is single-product) -----------------
#pragma unroll
    for (int nt = 0; nt < 8; nt++) {
        float* d = oac[nt];
        const int dd = nt * 8 + c00;
#pragma unroll
        for (int half = 0; half < 2; half++) {
            const int tok = blk * BSZ + ilow + half * 8;
            __half2 hv = __floats2half2_rn(d[2 * half], d[2 * half + 1]);
            size_t o = ((size_t)(b * NN) + tok) * CC + hd * DDIM + dd;
            *(__half2*)&g_ohi[o] = hv;
        }
    }
}

// ---------------- launch ------------------------------------------------------
extern "C" void kernel_launch(void* const* d_in, const int* in_sizes, int n_in,
                              void* d_out, int out_size)
{
    const float* x  = (const float*)d_in[0];
    const float* Wq = (const float*)d_in[1];
    const float* bq = (const float*)d_in[2];
    const float* Wk = (const float*)d_in[3];
    const float* bk = (const float*)d_in[4];
    const float* Wv = (const float*)d_in[5];
    const float* bv = (const float*)d_in[6];
    const float* Wo = (const float*)d_in[7];
    const float* bo = (const float*)d_in[8];
    float* out = (float*)d_out;

    cudaFuncSetAttribute(attn_mma,
                         cudaFuncAttributeMaxDynamicSharedMemorySize, ATT_SMEM);
    cudaFuncSetAttribute(gemm_mma<0>,
                         cudaFuncAttributeMaxDynamicSharedMemorySize, GEMM_SMEM);
    cudaFuncSetAttribute(gemm_mma<1>,
                         cudaFuncAttributeMaxDynamicSharedMemorySize, GEMM_SMEM);

    // fp32 -> fp16
    {
        int n4 = MTOT * CC / 4;
        convert_kernel<<<(n4 + 255) / 256, 256>>>(x, 0, n4);
        int w4 = CC * CC / 4;
        convert_kernel<<<(w4 + 255) / 256, 256>>>(Wq, 1, w4);
        convert_kernel<<<(w4 + 255) / 256, 256>>>(Wk, 2, w4);
        convert_kernel<<<(w4 + 255) / 256, 256>>>(Wv, 3, w4);
        convert_kernel<<<(w4 + 255) / 256, 256>>>(Wo, 4, w4);
    }

    // QKV projections (HMMA single-product), epilogue writes split-fp16 q/k/v
    dim3 g1(MTOT / 128, CC / 128, 3);
    gemm_mma<0><<<g1, 256, GEMM_SMEM>>>(bq, bk, bv, nullptr);

    // block-sparse attention on HMMA (3-product, fp32-equivalent)
    attn_mma<<<dim3(NBLK, HH, BB), 128, ATT_SMEM>>>();

    // output projection (single-product)
    dim3 g2(MTOT / 128, CC / 128, 1);
    gemm_mma<1><<<g2, 256, GEMM_SMEM>>>(bo, nullptr, nullptr, out);
}

// round 12
// speedup vs baseline: 5.9835x; 2.3657x over previous
#include <cuda_runtime.h>
#include <cuda_fp16.h>
#include <math.h>
#include <stdint.h>

// Problem constants
#define BB   4
#define NN   4096
#define CC   1024
#define HH   16
#define DDIM 64
#define BSZ  64
#define NBLK 64
#define MTOT (BB*NN)   // 16384

// ---------------- scratch (device globals, allocation-free) ------------------
__device__ __half g_xhi[(size_t)MTOT*CC];       // fp16(x)
__device__ __half g_whi[(size_t)4*CC*CC];       // Wq,Wk,Wv,Wo fp16
__device__ __half g_qh[(size_t)BB*HH*NN*DDIM];  // q/k/v split-fp16 [b][h][n][d]
__device__ __half g_ql[(size_t)BB*HH*NN*DDIM];
__device__ __half g_kh[(size_t)BB*HH*NN*DDIM];
__device__ __half g_kl[(size_t)BB*HH*NN*DDIM];
__device__ __half g_vh[(size_t)BB*HH*NN*DDIM];
__device__ __half g_vl[(size_t)BB*HH*NN*DDIM];
__device__ __half g_ohi[(size_t)MTOT*CC];       // attention out [m][c] (hi only)

// ---------------- PTX helpers (base sm_103 target only) ----------------------
__device__ __forceinline__ uint32_t smem_u32(const void* p) {
    uint32_t a;
    asm("{ .reg .u64 t; cvta.to.shared.u64 t, %1; cvt.u32.u64 %0, t; }"
        : "=r"(a) : "l"(p));
    return a;
}
__device__ __forceinline__ void ldsm4(unsigned* r, uint32_t addr) {
    asm volatile("ldmatrix.sync.aligned.m8n8.x4.shared.b16 {%0,%1,%2,%3}, [%4];"
                 : "=r"(r[0]), "=r"(r[1]), "=r"(r[2]), "=r"(r[3]) : "r"(addr));
}
__device__ __forceinline__ void ldsm4t(unsigned* r, uint32_t addr) {
    asm volatile("ldmatrix.sync.aligned.m8n8.x4.trans.shared.b16 {%0,%1,%2,%3}, [%4];"
                 : "=r"(r[0]), "=r"(r[1]), "=r"(r[2]), "=r"(r[3]) : "r"(addr));
}
__device__ __forceinline__ void mma16816_f32(float* d, const unsigned* a, const unsigned* b) {
    asm volatile(
        "mma.sync.aligned.m16n8k16.row.col.f32.f16.f16.f32 "
        "{%0,%1,%2,%3}, {%4,%5,%6,%7}, {%8,%9}, {%0,%1,%2,%3};"
        : "+f"(d[0]), "+f"(d[1]), "+f"(d[2]), "+f"(d[3])
        : "r"(a[0]), "r"(a[1]), "r"(a[2]), "r"(a[3]), "r"(b[0]), "r"(b[1]));
}
__device__ __forceinline__ void cpasync16(uint32_t saddr, const void* g) {
    asm volatile("cp.async.cg.shared.global [%0], [%1], 16;" :: "r"(saddr), "l"(g));
}
#define CP_COMMIT()  asm volatile("cp.async.commit_group;" ::: "memory")
#define CP_WAIT1()   asm volatile("cp.async.wait_group 1;" ::: "memory")
#define CP_WAIT0()   asm volatile("cp.async.wait_group 0;" ::: "memory")

// ---------------- fp32 -> fp16 conversion ------------------------------------
__global__ void convert_x(const float* __restrict__ src, int n4)
{
    int i = blockIdx.x * blockDim.x + threadIdx.x;
    if (i >= n4) return;
    float4 v = ((const float4*)src)[i];
    ((__half2*)g_xhi)[i * 2]     = __floats2half2_rn(v.x, v.y);
    ((__half2*)g_xhi)[i * 2 + 1] = __floats2half2_rn(v.z, v.w);
}
// all four weights in one launch
__global__ void convert_w(const float* __restrict__ Wq, const float* __restrict__ Wk,
                          const float* __restrict__ Wv, const float* __restrict__ Wo,
                          int per4)
{
    int i = blockIdx.x * blockDim.x + threadIdx.x;
    if (i >= 4 * per4) return;
    int wsel = i / per4;
    int j    = i - wsel * per4;
    const float* src = (wsel == 0) ? Wq : (wsel == 1) ? Wk : (wsel == 2) ? Wv : Wo;
    float4 v = ((const float4*)src)[j];
    __half* hi = g_whi + (size_t)wsel * CC * CC;
    ((__half2*)hi)[j * 2]     = __floats2half2_rn(v.x, v.y);
    ((__half2*)hi)[j * 2 + 1] = __floats2half2_rn(v.z, v.w);
}

// ---------------- HMMA single-product GEMM, BK=64 ----------------------------
// OUT[m][c] = sum_k Xhi[m][k]*Whi[c][k] + bias[c]; CTA tile 128x128.
// 16 chunks of BK=64; 2-stage cp.async pipeline.
// smem rows: 64 cols * 2B = 128B data, padded to 144B (9 x 16B; gcd(9,8)=1
// -> ldmatrix phases conflict-free: bank base 4r mod 32 distinct for r mod 8).
#define TILE_B 18432            // 128 * 144
#define STAGE_B (2 * TILE_B)    // 36864
#define GEMM_SMEM (2 * STAGE_B) // 73728
#define NCHUNK 16

template<int MODE>
__global__ __launch_bounds__(256, 2)
void gemm_mma(const float* __restrict__ b0,
              const float* __restrict__ b1,
              const float* __restrict__ b2,
              float* __restrict__ out)
{
    extern __shared__ char smc[];
    const uint32_t sb = smem_u32(smc);
    const int t    = threadIdx.x;
    const int w    = t >> 5;
    const int lane = t & 31;
    const int wm   = w & 3;
    const int wn   = w >> 2;
    const int m0   = blockIdx.x * 128;
    const int n0   = blockIdx.y * 128;
    const int widx = (MODE == 0) ? (int)blockIdx.z : 3;

    const __half* Ahi = (MODE == 0) ? g_xhi : g_ohi;
    const __half* Bhi = g_whi + (size_t)widx * CC * CC;
    const float* bias = b0;
    if (MODE == 0) { if (blockIdx.z == 1) bias = b1; else if (blockIdx.z == 2) bias = b2; }

    float acc[2][8][4];
#pragma unroll
    for (int a = 0; a < 2; a++)
#pragma unroll
        for (int n = 0; n < 8; n++)
#pragma unroll
            for (int k = 0; k < 4; k++) acc[a][n][k] = 0.f;

    const uint32_t aoff = (uint32_t)((lane & 15) * 144 + (lane >> 4) * 16);
    const uint32_t boff = (uint32_t)(((lane & 7) + (lane >> 4) * 8) * 144 + ((lane >> 3) & 1) * 16);

    // copy roles: 2 tiles * 128 rows * 8 chunks = 2048 / 256 thr = 8 each
    auto issue = [&](int ch) {
        const int k0 = ch * 64;
        const uint32_t stage = sb + (uint32_t)((ch & 1) * STAGE_B);
#pragma unroll
        for (int i = 0; i < 8; i++) {
            int id   = i * 256 + t;
            int tile = id >> 10;
            int idx  = id & 1023;
            int r    = idx >> 3;
            int c    = idx & 7;
            const __half* gp = tile ? Bhi : Ahi;
            int row = (tile ? n0 : m0) + r;
            cpasync16(stage + (uint32_t)(tile * TILE_B + r * 144 + c * 16),
                      gp + (size_t)row * CC + k0 + c * 8);
        }
        CP_COMMIT();
    };

    issue(0);
    for (int ch = 0; ch < NCHUNK; ch++) {
        if (ch + 1 < NCHUNK) { issue(ch + 1); CP_WAIT1(); }
        else                 { CP_WAIT0(); }
        __syncthreads();

        const uint32_t stage = sb + (uint32_t)((ch & 1) * STAGE_B);
#pragma unroll
        for (int s = 0; s < 4; s++) {          // four k16 steps within BK=64
            unsigned ahi[2][4];
#pragma unroll
            for (int mt = 0; mt < 2; mt++)
                ldsm4(ahi[mt], stage + (uint32_t)((wm * 32 + mt * 16) * 144) + aoff + s * 32);
#pragma unroll
            for (int np = 0; np < 4; np++) {
                unsigned bhi[4];
                ldsm4(bhi, stage + TILE_B
                           + (uint32_t)((wn * 64 + np * 16) * 144) + boff + s * 32);
#pragma unroll
                for (int mt = 0; mt < 2; mt++) {
#pragma unroll
                    for (int nh = 0; nh < 2; nh++)
                        mma16816_f32(acc[mt][np * 2 + nh], ahi[mt], &bhi[2 * nh]);
                }
            }
        }
        __syncthreads();
    }

    // epilogue
    __half* dsthi = g_qh;
    __half* dstlo = g_ql;
    if (MODE == 0) {
        if (blockIdx.z == 1)      { dsthi = g_kh; dstlo = g_kl; }
        else if (blockIdx.z == 2) { dsthi = g_vh; dstlo = g_vl; }
    }

#pragma unroll
    for (int mt = 0; mt < 2; mt++) {
#pragma unroll
        for (int nt = 0; nt < 8; nt++) {
            float* d = acc[mt][nt];
            const int col = n0 + wn * 64 + nt * 8 + 2 * (lane & 3);
            const float bv0 = bias[col], bv1 = bias[col + 1];
            const int r0 = m0 + wm * 32 + mt * 16 + (lane >> 2);
#pragma unroll
            for (int half = 0; half < 2; half++) {
                const int r = r0 + half * 8;
                float2 v = make_float2(d[2 * half] + bv0, d[2 * half + 1] + bv1);
                if (MODE == 0) {
                    const int bb  = r >> 12;
                    const int tok = r & (NN - 1);
                    const int h   = col >> 6;
                    const int dd  = col & 63;
                    __half2 hv = __floats2half2_rn(v.x, v.y);
                    float2 hf = __half22float2(hv);
                    __half2 lv = __floats2half2_rn(v.x - hf.x, v.y - hf.y);
                    size_t o = (((size_t)bb * HH + h) * NN + tok) * DDIM + dd;
                    *(__half2*)&dsthi[o] = hv;
                    *(__half2*)&dstlo[o] = lv;
                } else {
                    *(float2*)&out[(size_t)r * CC + col] = v;
                }
            }
        }
    }
}

// ---------------- Attention on HMMA: one CTA (128 thr) per (b, h, blk) -------
// Window = blocks [blk-1, blk] (right block fully causal-masked). 3-product
// split-fp16 MMA (error ~2^-22): qk = qh*kh + qh*kl + ql*kh; pv similarly.
#define AQH 0
#define AQL 9216
#define AKH 18432
#define AKL 36864
#define AVH 55296
#define AVL 73728
#define ATT_SMEM 92160

__global__ __launch_bounds__(128, 2)
void attn_mma()
{
    extern __shared__ char smc[];
    const uint32_t sb = smem_u32(smc);
    const int blk = blockIdx.x;
    const int hd  = blockIdx.y;
    const int b   = blockIdx.z;
    const int t   = threadIdx.x;
    const int w   = t >> 5;
    const int lane = t & 31;

    const size_t base = ((size_t)(b * HH + hd)) * NN * DDIM;

#pragma unroll
    for (int i = 0; i < 4; i++) {
        int id = i * 128 + t;
        int r = id >> 3, c = id & 7;
        size_t o = base + (size_t)(blk * BSZ + r) * DDIM;
        *(uint4*)(smc + AQH + r * 144 + c * 16) = *((const uint4*)(g_qh + o) + c);
        *(uint4*)(smc + AQL + r * 144 + c * 16) = *((const uint4*)(g_ql + o) + c);
    }
#pragma unroll
    for (int i = 0; i < 8; i++) {
        int id = i * 128 + t;
        int r = id >> 3, c = id & 7;
        int tokrel = (blk - 1) * BSZ + r;
        uint4 z = make_uint4(0u, 0u, 0u, 0u);
        uint4 kh = z, kl = z, vh = z, vl = z;
        if (tokrel >= 0) {
            size_t o = base + (size_t)tokrel * DDIM;
            kh = *((const uint4*)(g_kh + o) + c);
            kl = *((const uint4*)(g_kl + o) + c);
            vh = *((const uint4*)(g_vh + o) + c);
            vl = *((const uint4*)(g_vl + o) + c);
        }
        *(uint4*)(smc + AKH + r * 144 + c * 16) = kh;
        *(uint4*)(smc + AKL + r * 144 + c * 16) = kl;
        *(uint4*)(smc + AVH + r * 144 + c * 16) = vh;
        *(uint4*)(smc + AVL + r * 144 + c * 16) = vl;
    }
    __syncthreads();

    const int mw = w * 16;
    float sc[16][4];
#pragma unroll
    for (int j = 0; j < 16; j++)
#pragma unroll
        for (int k = 0; k < 4; k++) sc[j][k] = 0.f;

    const uint32_t aoffQ = (uint32_t)((mw + (lane & 15)) * 144 + (lane >> 4) * 16);
    const uint32_t boffK = (uint32_t)(((lane & 7) + (lane >> 4) * 8) * 144 + ((lane >> 3) & 1) * 16);

#pragma unroll
    for (int s = 0; s < 4; s++) {
        unsigned aq[4], al[4];
        ldsm4(aq, sb + AQH + aoffQ + s * 32);
        ldsm4(al, sb + AQL + aoffQ + s * 32);
#pragma unroll
        for (int g = 0; g < 8; g++) {
            unsigned bh[4], bl[4];
            uint32_t ka = sb + AKH + boffK + (uint32_t)(g * 16 * 144) + s * 32;
            ldsm4(bh, ka);
            ldsm4(bl, ka + (AKL - AKH));
#pragma unroll
            for (int nh = 0; nh < 2; nh++) {
                float* d = sc[g * 2 + nh];
                mma16816_f32(d, aq, &bh[2 * nh]);
                mma16816_f32(d, aq, &bl[2 * nh]);
                mma16816_f32(d, al, &bh[2 * nh]);
            }
        }
    }

    const int ilow = mw + (lane >> 2);
    const int c00  = 2 * (lane & 3);
    float mx0 = -1e30f, mx1 = -1e30f;
#pragma unroll
    for (int j = 0; j < 16; j++) {
        int c0 = j * 8 + c00;
        bool kv0 = (c0     >= 64) || (blk > 0);
        bool kv1 = (c0 + 1 >= 64) || (blk > 0);
        bool v0a = (c0     <= 64 + ilow) && kv0;
        bool v1a = (c0 + 1 <= 64 + ilow) && kv1;
        bool v0b = (c0     <= 72 + ilow) && kv0;
        bool v1b = (c0 + 1 <= 72 + ilow) && kv1;
        sc[j][0] = v0a ? sc[j][0] * 0.125f : -1e30f;
        sc[j][1] = v1a ? sc[j][1] * 0.125f : -1e30f;
        sc[j][2] = v0b ? sc[j][2] * 0.125f : -1e30f;
        sc[j][3] = v1b ? sc[j][3] * 0.125f : -1e30f;
        mx0 = fmaxf(mx0, fmaxf(sc[j][0], sc[j][1]));
        mx1 = fmaxf(mx1, fmaxf(sc[j][2], sc[j][3]));
    }
    mx0 = fmaxf(mx0, __shfl_xor_sync(0xffffffffu, mx0, 1));
    mx0 = fmaxf(mx0, __shfl_xor_sync(0xffffffffu, mx0, 2));
    mx1 = fmaxf(mx1, __shfl_xor_sync(0xffffffffu, mx1, 1));
    mx1 = fmaxf(mx1, __shfl_xor_sync(0xffffffffu, mx1, 2));

    float sm0 = 0.f, sm1 = 0.f;
#pragma unroll
    for (int j = 0; j < 16; j++) {
        sc[j][0] = __expf(sc[j][0] - mx0);
        sc[j][1] = __expf(sc[j][1] - mx0);
        sc[j][2] = __expf(sc[j][2] - mx1);
        sc[j][3] = __expf(sc[j][3] - mx1);
        sm0 += sc[j][0] + sc[j][1];
        sm1 += sc[j][2] + sc[j][3];
    }
    sm0 += __shfl_xor_sync(0xffffffffu, sm0, 1);
    sm0 += __shfl_xor_sync(0xffffffffu, sm0, 2);
    sm1 += __shfl_xor_sync(0xffffffffu, sm1, 1);
    sm1 += __shfl_xor_sync(0xffffffffu, sm1, 2);
    const float inv0 = 1.f / sm0, inv1 = 1.f / sm1;

    unsigned pa[8][4], pl[8][4];
#pragma unroll
    for (int j = 0; j < 8; j++) {
#pragma unroll
        for (int half = 0; half < 2; half++) {
            float p0 = sc[2 * j + half][0] * inv0;
            float p1 = sc[2 * j + half][1] * inv0;
            float p2 = sc[2 * j + half][2] * inv1;
            float p3 = sc[2 * j + half][3] * inv1;
            __half2 h01 = __floats2half2_rn(p0, p1);
            __half2 h23 = __floats2half2_rn(p2, p3);
            float2 f01 = __half22float2(h01);
            float2 f23 = __half22float2(h23);
            __half2 l01 = __floats2half2_rn(p0 - f01.x, p1 - f01.y);
            __half2 l23 = __floats2half2_rn(p2 - f23.x, p3 - f23.y);
            pa[j][2 * half]     = *(unsigned*)&h01;
            pa[j][2 * half + 1] = *(unsigned*)&h23;
            pl[j][2 * half]     = *(unsigned*)&l01;
            pl[j][2 * half + 1] = *(unsigned*)&l23;
        }
    }

    float oac[8][4];
#pragma unroll
    for (int n = 0; n < 8; n++)
#pragma unroll
        for (int k = 0; k < 4; k++) oac[n][k] = 0.f;

#pragma unroll
    for (int j = 0; j < 8; j++) {
#pragma unroll
        for (int g = 0; g < 4; g++) {
            unsigned bh[4], bl[4];
            uint32_t va = sb + AVH
                        + (uint32_t)((j * 16 + (lane & 15)) * 144)
                        + (uint32_t)((g * 16 + (lane >> 4) * 8) * 2);
            ldsm4t(bh, va);
            ldsm4t(bl, va + (AVL - AVH));
#pragma unroll
            for (int nh = 0; nh < 2; nh++) {
                float* d = oac[g * 2 + nh];
                mma16816_f32(d, pa[j], &bh[2 * nh]);
                mma16816_f32(d, pa[j], &bl[2 * nh]);
                mma16816_f32(d, pl[j], &bh[2 * nh]);
            }
        }
    }

#pragma unroll
    for (int nt = 0; nt < 8; nt++) {
        float* d = oac[nt];
        const int dd = nt * 8 + c00;
#pragma unroll
        for (int half = 0; half < 2; half++) {
            const int tok = blk * BSZ + ilow + half * 8;
            __half2 hv = __floats2half2_rn(d[2 * half], d[2 * half + 1]);
            size_t o = ((size_t)(b * NN) + tok) * CC + hd * DDIM + dd;
            *(__half2*)&g_ohi[o] = hv;
        }
    }
}

// ---------------- launch ------------------------------------------------------
extern "C" void kernel_launch(void* const* d_in, const int* in_sizes, int n_in,
                              void* d_out, int out_size)
{
    const float* x  = (const float*)d_in[0];
    const float* Wq = (const float*)d_in[1];
    const float* bq = (const float*)d_in[2];
    const float* Wk = (const float*)d_in[3];
    const float* bk = (const float*)d_in[4];
    const float* Wv = (const float*)d_in[5];
    const float* bv = (const float*)d_in[6];
    const float* Wo = (const float*)d_in[7];
    const float* bo = (const float*)d_in[8];
    float* out = (float*)d_out;

    cudaFuncSetAttribute(attn_mma,
                         cudaFuncAttributeMaxDynamicSharedMemorySize, ATT_SMEM);
    cudaFuncSetAttribute(gemm_mma<0>,
                         cudaFuncAttributeMaxDynamicSharedMemorySize, GEMM_SMEM);
    cudaFuncSetAttribute(gemm_mma<1>,
                         cudaFuncAttributeMaxDynamicSharedMemorySize, GEMM_SMEM);

    // fp32 -> fp16 (2 launches)
    {
        int n4 = MTOT * CC / 4;
        convert_x<<<(n4 + 255) / 256, 256>>>(x, n4);
        int w4 = CC * CC / 4;
        convert_w<<<(4 * w4 + 255) / 256, 256>>>(Wq, Wk, Wv, Wo, w4);
    }

    // QKV projections (HMMA single-product, BK=64), writes split-fp16 q/k/v
    dim3 g1(MTOT / 128, CC / 128, 3);
    gemm_mma<0><<<g1, 256, GEMM_SMEM>>>(bq, bk, bv, nullptr);

    // block-sparse attention on HMMA (3-product, fp32-equivalent)
    attn_mma<<<dim3(NBLK, HH, BB), 128, ATT_SMEM>>>();

    // output projection (single-product, BK=64)
    dim3 g2(MTOT / 128, CC / 128, 1);
    gemm_mma<1><<<g2, 256, GEMM_SMEM>>>(bo, nullptr, nullptr, out);
}